// round 9
// baseline (speedup 1.0000x reference)
#include <cuda_runtime.h>
#include <math_constants.h>
#include <cstdint>

// Problem constants: B=16,T=2048,D=256,K=4096
#define N_TOK 32768
#define DIM   256
#define KCB   4096
#define NKCH  (DIM / 4)     // 64 packed int32 k-chunks per row

#define TOK_TILE  128
#define CODE_TILE 128
#define N_CTILE   (KCB / CODE_TILE)   // 32
#define MAX_CAND  64

// ---------------- device scratch (no allocations allowed) -------------------
__device__ float  g_S[N_TOK];
__device__ float  g_c[KCB];
__device__ float  g_loss[N_TOK];
__device__ double g_part[128];
__device__ float  g_sx[N_TOK], g_Lx[N_TOK];
__device__ float  g_se[KCB],  g_Le[KCB];
__device__ float  g_maxse, g_maxLe;
__device__ __align__(16) int g_XqT[NKCH * N_TOK];   // [kchunk][token]  8MB
__device__ __align__(16) int g_EqT[NKCH * KCB];     // [kchunk][code]   1MB
__device__ unsigned short g_cand[N_TOK][MAX_CAND];
__device__ float  g_cand_s[N_TOK][MAX_CAND];        // coarse score per candidate
__device__ int    g_ncand[N_TOK];

// ---------------- helpers ----------------------------------------------------
__device__ __forceinline__ uint32_t smem_to_u32(const void* p) {
    uint32_t a;
    asm("{ .reg .u64 t; cvta.to.shared.u64 t, %1; cvt.u32.u64 %0, t; }" : "=r"(a) : "l"(p));
    return a;
}
__device__ __forceinline__ void dp4a(int& acc, int a, int b) {
    asm("dp4a.s32.s32 %0, %1, %2, %0;" : "+r"(acc) : "r"(a), "r"(b));
}
__device__ __forceinline__ void cp_async16(uint32_t dst_smem, const void* src) {
    asm volatile("cp.async.cg.shared.global [%0], [%1], 16;" :: "r"(dst_smem), "l"(src) : "memory");
}
__device__ __forceinline__ void cp_commit() { asm volatile("cp.async.commit_group;" ::: "memory"); }
__device__ __forceinline__ void cp_wait0()  { asm volatile("cp.async.wait_group 0;"  ::: "memory"); }
__device__ __forceinline__ int q8(float v, float inv) {
    int q = __float2int_rn(v * inv);
    return max(-127, min(127, q));
}
// rigorous per-token margin: 2*(int8 quant bound on 2m) + fp32 d2-chain slop
__device__ __forceinline__ float token_margin(float sx, float lx, float mse, float mle) {
    return 2.0f * (0.5f * sx * mle + 0.5f * mse * lx + 128.0f * sx * mse) + 3.0e-4f;
}

// ---------------------------------------------------------------------------
// Kernel 1: per-row exact-fp32 sums of squares (bit-matching R2 chain),
// per-row max/L1, int8 quantization into TRANSPOSED packed layout.
// ---------------------------------------------------------------------------
__global__ void prep_kernel(const float* __restrict__ X, const float* __restrict__ E) {
    int i = blockIdx.x * blockDim.x + threadIdx.x;
    if (i < N_TOK) {
        g_ncand[i] = 0;
        const float4* row = reinterpret_cast<const float4*>(X + (size_t)i * DIM);
        float s = 0.0f, mx = 0.0f, l1 = 0.0f;
        #pragma unroll 8
        for (int j = 0; j < DIM / 4; j++) {
            float4 v = row[j];
            s = __fadd_rn(s, __fmul_rn(v.x, v.x));
            s = __fadd_rn(s, __fmul_rn(v.y, v.y));
            s = __fadd_rn(s, __fmul_rn(v.z, v.z));
            s = __fadd_rn(s, __fmul_rn(v.w, v.w));
            float ax = fabsf(v.x), ay = fabsf(v.y), az = fabsf(v.z), aw = fabsf(v.w);
            mx = fmaxf(fmaxf(mx, ax), fmaxf(ay, fmaxf(az, aw)));
            l1 += ax + ay + az + aw;
        }
        g_S[i] = s;
        mx = fmaxf(mx, 1e-30f);
        float inv = 127.0f / mx;
        g_sx[i] = mx / 127.0f;
        g_Lx[i] = l1;
        #pragma unroll 8
        for (int k = 0; k < NKCH; k++) {
            float4 v = row[k];
            int q0 = q8(v.x, inv), q1 = q8(v.y, inv), q2 = q8(v.z, inv), q3 = q8(v.w, inv);
            g_XqT[k * N_TOK + i] = (q0 & 255) | ((q1 & 255) << 8) | ((q2 & 255) << 16) | ((q3 & 255) << 24);
        }
    }
    if (i < KCB) {
        const float4* row = reinterpret_cast<const float4*>(E + (size_t)i * DIM);
        float s = 0.0f, mx = 0.0f, l1 = 0.0f;
        #pragma unroll 8
        for (int j = 0; j < DIM / 4; j++) {
            float4 v = row[j];
            s = __fadd_rn(s, __fmul_rn(v.x, v.x));
            s = __fadd_rn(s, __fmul_rn(v.y, v.y));
            s = __fadd_rn(s, __fmul_rn(v.z, v.z));
            s = __fadd_rn(s, __fmul_rn(v.w, v.w));
            float ax = fabsf(v.x), ay = fabsf(v.y), az = fabsf(v.z), aw = fabsf(v.w);
            mx = fmaxf(fmaxf(mx, ax), fmaxf(ay, fmaxf(az, aw)));
            l1 += ax + ay + az + aw;
        }
        g_c[i] = s;
        mx = fmaxf(mx, 1e-30f);
        float inv = 127.0f / mx;
        g_se[i] = mx / 127.0f;
        g_Le[i] = l1;
        #pragma unroll 8
        for (int k = 0; k < NKCH; k++) {
            float4 v = row[k];
            int q0 = q8(v.x, inv), q1 = q8(v.y, inv), q2 = q8(v.z, inv), q3 = q8(v.w, inv);
            g_EqT[k * KCB + i] = (q0 & 255) | ((q1 & 255) << 8) | ((q2 & 255) << 16) | ((q3 & 255) << 24);
        }
    }
}

// ---------------------------------------------------------------------------
// Kernel 2: global max of se / Le over codes (for rigorous per-token margins).
// ---------------------------------------------------------------------------
__global__ void reduce_kernel() {
    __shared__ float s1[256], s2[256];
    float m1 = 0.0f, m2 = 0.0f;
    for (int j = threadIdx.x; j < KCB; j += 256) {
        m1 = fmaxf(m1, g_se[j]);
        m2 = fmaxf(m2, g_Le[j]);
    }
    s1[threadIdx.x] = m1; s2[threadIdx.x] = m2;
    __syncthreads();
    for (int off = 128; off >= 1; off >>= 1) {
        if (threadIdx.x < off) {
            s1[threadIdx.x] = fmaxf(s1[threadIdx.x], s1[threadIdx.x + off]);
            s2[threadIdx.x] = fmaxf(s2[threadIdx.x], s2[threadIdx.x + off]);
        }
        __syncthreads();
    }
    if (threadIdx.x == 0) { g_maxse = s1[0]; g_maxLe = s2[0]; }
}

// ---------------------------------------------------------------------------
// Kernel 3: int8 dp4a coarse GEMM + margin candidate collection.
// CTA = 128 tokens x 4096 codes (32 tiles of 128). 256 threads as 16(ty)x16(tx),
// 8 tokens x 8 codes per thread, exact int32 dots. Token-global running min
// via half-warp shfl (16 code-lanes of a token share a half-warp).
// Candidates (code, coarse score) stored for the rescore filter.
// ---------------------------------------------------------------------------
#define SM_X    0                     // int Xs[64][128]            32KB
#define SM_E    32768                 // int Es[2][64][128]         64KB
#define SM_MARG 98304                 // float marg[128]
#define SM_SX   98816                 // float sx[128]
#define SMEM_TOTAL 99328

__global__ __launch_bounds__(256) void coarse_kernel() {
    extern __shared__ __align__(16) char smem[];
    const int tid = threadIdx.x;
    const int tx = tid & 15, ty = tid >> 4;
    const int mb = blockIdx.x * TOK_TILE;
    uint32_t sb = smem_to_u32(smem);
    int* Xs = reinterpret_cast<int*>(smem + SM_X);
    int* Es = reinterpret_cast<int*>(smem + SM_E);
    float* marg_s = reinterpret_cast<float*>(smem + SM_MARG);
    float* sx_s = reinterpret_cast<float*>(smem + SM_SX);

    if (tid < TOK_TILE) {
        float sx = g_sx[mb + tid];
        float lx = g_Lx[mb + tid];
        sx_s[tid] = sx;
        marg_s[tid] = token_margin(sx, lx, g_maxse, g_maxLe);
    }

    // X tile: 64 kchunks x 128 tokens (cp.async, contiguous 512B rows)
    #pragma unroll
    for (int k = 0; k < 8; k++) {
        int v = tid + k * 256;
        int row = v >> 5, ch = v & 31;
        cp_async16(sb + SM_X + (row * 128 + ch * 4) * 4,
                   g_XqT + (size_t)row * N_TOK + mb + ch * 4);
    }
    // E tile 0
    #pragma unroll
    for (int k = 0; k < 8; k++) {
        int v = tid + k * 256;
        int row = v >> 5, ch = v & 31;
        cp_async16(sb + SM_E + (row * 128 + ch * 4) * 4,
                   g_EqT + (size_t)row * KCB + ch * 4);
    }
    cp_commit();
    cp_wait0();
    __syncthreads();

    float sxv[8], margv[8], runmin[8];
    #pragma unroll
    for (int i = 0; i < 8; i++) {
        sxv[i]   = sx_s[ty * 8 + i];
        margv[i] = marg_s[ty * 8 + i];
        runmin[i] = CUDART_INF_F;
    }

    for (int ct = 0; ct < N_CTILE; ct++) {
        const int cur = ct & 1;

        if (ct < N_CTILE - 1) {
            #pragma unroll
            for (int k = 0; k < 8; k++) {
                int v = tid + k * 256;
                int row = v >> 5, ch = v & 31;
                cp_async16(sb + SM_E + ((cur ^ 1) * 8192 + row * 128 + ch * 4) * 4,
                           g_EqT + (size_t)row * KCB + (ct + 1) * CODE_TILE + ch * 4);
            }
            cp_commit();
        }

        int acc[8][8];
        #pragma unroll
        for (int i = 0; i < 8; i++)
            #pragma unroll
            for (int j = 0; j < 8; j++) acc[i][j] = 0;

        const int* eb = Es + cur * 8192;
        #pragma unroll 4
        for (int kc = 0; kc < NKCH; kc++) {
            int4 a0 = *reinterpret_cast<const int4*>(Xs + kc * 128 + ty * 8);
            int4 a1 = *reinterpret_cast<const int4*>(Xs + kc * 128 + ty * 8 + 4);
            int4 b0 = *reinterpret_cast<const int4*>(eb + kc * 128 + tx * 8);
            int4 b1 = *reinterpret_cast<const int4*>(eb + kc * 128 + tx * 8 + 4);
            int aw[8] = {a0.x, a0.y, a0.z, a0.w, a1.x, a1.y, a1.z, a1.w};
            int bw[8] = {b0.x, b0.y, b0.z, b0.w, b1.x, b1.y, b1.z, b1.w};
            #pragma unroll
            for (int i = 0; i < 8; i++)
                #pragma unroll
                for (int j = 0; j < 8; j++)
                    dp4a(acc[i][j], aw[i], bw[j]);
        }

        // epilogue: s_hat, half-warp tile-min reduce, running-min collection
        float se8[8], c8[8];
        #pragma unroll
        for (int j = 0; j < 8; j++) {
            int code = ct * CODE_TILE + tx * 8 + j;
            se8[j] = __ldg(&g_se[code]);
            c8[j]  = __ldg(&g_c[code]);
        }
        #pragma unroll
        for (int i = 0; i < 8; i++) {
            const float nsx = -2.0f * sxv[i];
            float s[8];
            float tmin = CUDART_INF_F;
            #pragma unroll
            for (int j = 0; j < 8; j++) {
                s[j] = fmaf(nsx * se8[j], (float)acc[i][j], c8[j]);
                tmin = fminf(tmin, s[j]);
            }
            // reduce tile-min across the 16 code-lanes (same half-warp)
            #pragma unroll
            for (int off = 8; off >= 1; off >>= 1)
                tmin = fminf(tmin, __shfl_xor_sync(0xffffffffu, tmin, off));
            runmin[i] = fminf(runmin[i], tmin);
            const float th = runmin[i] + margv[i];
            bool any = false;
            #pragma unroll
            for (int j = 0; j < 8; j++) any |= (s[j] <= th);
            if (any) {
                const int token = mb + ty * 8 + i;
                #pragma unroll
                for (int j = 0; j < 8; j++) {
                    if (s[j] <= th) {
                        int code = ct * CODE_TILE + tx * 8 + j;
                        int p = atomicAdd(&g_ncand[token], 1);
                        if (p < MAX_CAND) {
                            g_cand[token][p] = (unsigned short)code;
                            g_cand_s[token][p] = s[j];
                        }
                    }
                }
            }
        }

        if (ct < N_CTILE - 1) cp_wait0();
        __syncthreads();
    }
}

// ---------------------------------------------------------------------------
// Kernel 4: survivor-filtered exact rescore + gather + STE output + loss.
// One warp per token.
//  - survivors = candidates with coarse s <= finalmin + marg. The exact fp32
//    argmin (and all exact ties) are provably survivors; non-survivors have
//    strictly larger exact d2.
//  - 1 survivor  -> it IS the argmin; no dot products at all.
//  - >1 survivor -> exact R2-chain d2 on surviving lanes only, lexicographic min.
//  - overflow (n > MAX_CAND, ~never) -> exact full scan.
// ---------------------------------------------------------------------------
__global__ void rescore_output_kernel(const float* __restrict__ X, const float* __restrict__ E,
                                      float* __restrict__ out_q, float* __restrict__ out_idx_f) {
    int token = (blockIdx.x * blockDim.x + threadIdx.x) >> 5;
    int lane = threadIdx.x & 31;
    if (token >= N_TOK) return;
    int n = g_ncand[token];
    float S = g_S[token];
    const float4* xr = reinterpret_cast<const float4*>(X + (size_t)token * DIM);

    int besti = 0x7fffffff;

    if (n <= MAX_CAND) {
        // load up to 2 candidate slots per lane
        float s0 = CUDART_INF_F, s1 = CUDART_INF_F;
        int   c0 = 0x7fffffff,  c1 = 0x7fffffff;
        if (lane < n)      { c0 = g_cand[token][lane];      s0 = g_cand_s[token][lane]; }
        if (lane + 32 < n) { c1 = g_cand[token][lane + 32]; s1 = g_cand_s[token][lane + 32]; }
        // warp min of coarse scores
        float fm = fminf(s0, s1);
        #pragma unroll
        for (int off = 16; off >= 1; off >>= 1)
            fm = fminf(fm, __shfl_xor_sync(0xffffffffu, fm, off));
        const float marg = token_margin(g_sx[token], g_Lx[token], g_maxse, g_maxLe);
        const float th = fm + marg;
        bool sv0 = (lane < n) && (s0 <= th);
        bool sv1 = (lane + 32 < n) && (s1 <= th);
        unsigned m0 = __ballot_sync(0xffffffffu, sv0);
        unsigned m1 = __ballot_sync(0xffffffffu, sv1);
        int tot = __popc(m0) + __popc(m1);
        if (tot == 1) {
            int src = m0 ? (__ffs(m0) - 1) : (__ffs(m1) - 1);
            int v = sv0 ? c0 : c1;      // on src lane this selects the survivor
            besti = __shfl_sync(0xffffffffu, (m0 ? c0 : v), src);
            if (!m0) besti = __shfl_sync(0xffffffffu, c1, src);
        } else {
            float bestv = CUDART_INF_F;
            #pragma unroll
            for (int slot = 0; slot < 2; slot++) {
                bool sv = slot == 0 ? sv0 : sv1;
                int  cd = slot == 0 ? c0 : c1;
                if (sv) {
                    const float4* er = reinterpret_cast<const float4*>(E + (size_t)cd * DIM);
                    float m = 0.0f;
                    #pragma unroll 8
                    for (int k = 0; k < DIM / 4; k++) {
                        float4 x = xr[k], e = er[k];
                        m = fmaf(x.x, e.x, m); m = fmaf(x.y, e.y, m);
                        m = fmaf(x.z, e.z, m); m = fmaf(x.w, e.w, m);
                    }
                    float t = fmaf(-2.0f, m, S);
                    float d2 = __fadd_rn(t, g_c[cd]);
                    if (d2 < bestv || (d2 == bestv && cd < besti)) { bestv = d2; besti = cd; }
                }
            }
            #pragma unroll
            for (int off = 16; off >= 1; off >>= 1) {
                float ov = __shfl_xor_sync(0xffffffffu, bestv, off);
                int   oi = __shfl_xor_sync(0xffffffffu, besti, off);
                if (ov < bestv || (ov == bestv && oi < besti)) { bestv = ov; besti = oi; }
            }
            besti = __shfl_sync(0xffffffffu, besti, 0);
        }
    } else {
        // overflow fallback: exact scan of all codes (rare)
        float bestv = CUDART_INF_F;
        for (int code = lane; code < KCB; code += 32) {
            const float4* er = reinterpret_cast<const float4*>(E + (size_t)code * DIM);
            float m = 0.0f;
            #pragma unroll 8
            for (int k = 0; k < DIM / 4; k++) {
                float4 x = xr[k], e = er[k];
                m = fmaf(x.x, e.x, m); m = fmaf(x.y, e.y, m);
                m = fmaf(x.z, e.z, m); m = fmaf(x.w, e.w, m);
            }
            float t = fmaf(-2.0f, m, S);
            float d2 = __fadd_rn(t, g_c[code]);
            if (d2 < bestv || (d2 == bestv && code < besti)) { bestv = d2; besti = code; }
        }
        #pragma unroll
        for (int off = 16; off >= 1; off >>= 1) {
            float ov = __shfl_xor_sync(0xffffffffu, bestv, off);
            int   oi = __shfl_xor_sync(0xffffffffu, besti, off);
            if (ov < bestv || (ov == bestv && oi < besti)) { bestv = ov; besti = oi; }
        }
        besti = __shfl_sync(0xffffffffu, besti, 0);
    }

    // gather + straight-through + loss (bit-exact R2 arithmetic)
    const float4* er = reinterpret_cast<const float4*>(E + (size_t)besti * DIM);
    float* qr = out_q + (size_t)token * DIM;   // 4B-aligned only -> scalar stores
    float ls = 0.0f;
    #pragma unroll
    for (int j = lane; j < DIM / 4; j += 32) {
        float4 x = xr[j], e = er[j];
        float4 d, o;
        d.x = __fadd_rn(e.x, -x.x); d.y = __fadd_rn(e.y, -x.y);
        d.z = __fadd_rn(e.z, -x.z); d.w = __fadd_rn(e.w, -x.w);
        ls = __fadd_rn(ls, __fmul_rn(d.x, d.x));
        ls = __fadd_rn(ls, __fmul_rn(d.y, d.y));
        ls = __fadd_rn(ls, __fmul_rn(d.z, d.z));
        ls = __fadd_rn(ls, __fmul_rn(d.w, d.w));
        o.x = __fadd_rn(x.x, d.x); o.y = __fadd_rn(x.y, d.y);
        o.z = __fadd_rn(x.z, d.z); o.w = __fadd_rn(x.w, d.w);
        qr[j * 4 + 0] = o.x;
        qr[j * 4 + 1] = o.y;
        qr[j * 4 + 2] = o.z;
        qr[j * 4 + 3] = o.w;
    }
    #pragma unroll
    for (int off = 16; off >= 1; off >>= 1)
        ls = __fadd_rn(ls, __shfl_xor_sync(0xffffffffu, ls, off));
    if (lane == 0) {
        g_loss[token] = ls;
        out_idx_f[token] = (float)besti;
    }
}

// ---------------------------------------------------------------------------
// Kernels 5+6: two-stage deterministic double-precision loss reduction.
// ---------------------------------------------------------------------------
__global__ void finalize1_kernel() {
    __shared__ double sh[256];
    int b = blockIdx.x;
    sh[threadIdx.x] = (double)g_loss[b * 256 + threadIdx.x];
    __syncthreads();
    for (int off = 128; off >= 1; off >>= 1) {
        if (threadIdx.x < off) sh[threadIdx.x] += sh[threadIdx.x + off];
        __syncthreads();
    }
    if (threadIdx.x == 0) g_part[b] = sh[0];
}
__global__ void finalize2_kernel(float* __restrict__ out) {
    __shared__ double sh[128];
    sh[threadIdx.x] = g_part[threadIdx.x];
    __syncthreads();
    for (int off = 64; off >= 1; off >>= 1) {
        if (threadIdx.x < off) sh[threadIdx.x] += sh[threadIdx.x + off];
        __syncthreads();
    }
    if (threadIdx.x == 0)
        out[0] = (float)(0.5 * sh[0] / ((double)N_TOK * (double)DIM));
}

// ---------------------------------------------------------------------------
extern "C" void kernel_launch(void* const* d_in, const int* in_sizes, int n_in,
                              void* d_out, int out_size) {
    const float* X = (const float*)d_in[0];   // embedding_tokens [N, D]
    const float* E = (const float*)d_in[1];   // embeddings       [K, D]
    float* out = (float*)d_out;
    float* out_q   = out + 1;
    float* out_idx = out + 1 + (size_t)N_TOK * DIM;

    static int smem_set = 0;
    if (!smem_set) {
        cudaFuncSetAttribute(coarse_kernel, cudaFuncAttributeMaxDynamicSharedMemorySize, SMEM_TOTAL);
        smem_set = 1;
    }

    prep_kernel<<<N_TOK / 256, 256>>>(X, E);
    reduce_kernel<<<1, 256>>>();
    coarse_kernel<<<N_TOK / TOK_TILE, 256, SMEM_TOTAL>>>();
    rescore_output_kernel<<<(N_TOK * 32) / 256, 256>>>(X, E, out_q, out_idx);
    finalize1_kernel<<<128, 256>>>();
    finalize2_kernel<<<1, 128>>>(out);
}

// round 10
// speedup vs baseline: 2.0208x; 2.0208x over previous
#include <cuda_runtime.h>
#include <math_constants.h>
#include <cstdint>

// Problem constants: B=16,T=2048,D=256,K=4096
#define N_TOK 32768
#define DIM   256
#define KCB   4096
#define NKCH  (DIM / 4)     // 64 packed int32 k-chunks per row

#define TOK_TILE  128
#define CODE_TILE 128
#define N_CTILE   (KCB / CODE_TILE)   // 32
#define MAX_CAND  128

// ---------------- device scratch (no allocations allowed) -------------------
__device__ float  g_S[N_TOK];
__device__ float  g_c[KCB];
__device__ float  g_loss[N_TOK];
__device__ double g_part[128];
__device__ float  g_sx[N_TOK], g_Lx[N_TOK];
__device__ float  g_se[KCB],  g_Le[KCB];
__device__ float  g_maxse, g_maxLe;
__device__ __align__(16) int g_XqT[NKCH * N_TOK];   // [kchunk][token]  8MB
__device__ __align__(16) int g_EqT[NKCH * KCB];     // [kchunk][code]   1MB
__device__ unsigned short g_cand[N_TOK][MAX_CAND];  // 8MB
__device__ float  g_cand_s[N_TOK][MAX_CAND];        // 16MB coarse scores
__device__ int    g_ncand[N_TOK];

// ---------------- helpers ----------------------------------------------------
__device__ __forceinline__ uint32_t smem_to_u32(const void* p) {
    uint32_t a;
    asm("{ .reg .u64 t; cvta.to.shared.u64 t, %1; cvt.u32.u64 %0, t; }" : "=r"(a) : "l"(p));
    return a;
}
__device__ __forceinline__ void dp4a(int& acc, int a, int b) {
    asm("dp4a.s32.s32 %0, %1, %2, %0;" : "+r"(acc) : "r"(a), "r"(b));
}
__device__ __forceinline__ void cp_async16(uint32_t dst_smem, const void* src) {
    asm volatile("cp.async.cg.shared.global [%0], [%1], 16;" :: "r"(dst_smem), "l"(src) : "memory");
}
__device__ __forceinline__ void cp_commit() { asm volatile("cp.async.commit_group;" ::: "memory"); }
__device__ __forceinline__ void cp_wait0()  { asm volatile("cp.async.wait_group 0;"  ::: "memory"); }
__device__ __forceinline__ int q8(float v, float inv) {
    int q = __float2int_rn(v * inv);
    return max(-127, min(127, q));
}
// rigorous per-token margin: 2*(int8 quant bound on 2m) + fp32 d2-chain slop
__device__ __forceinline__ float token_margin(float sx, float lx, float mse, float mle) {
    return 2.0f * (0.5f * sx * mle + 0.5f * mse * lx + 128.0f * sx * mse) + 3.0e-4f;
}

// ---------------------------------------------------------------------------
// Kernel 1: per-row exact-fp32 sums of squares (bit-matching R2 chain),
// per-row max/L1, int8 quantization into TRANSPOSED packed layout.
// ---------------------------------------------------------------------------
__global__ void prep_kernel(const float* __restrict__ X, const float* __restrict__ E) {
    int i = blockIdx.x * blockDim.x + threadIdx.x;
    if (i < N_TOK) {
        g_ncand[i] = 0;
        const float4* row = reinterpret_cast<const float4*>(X + (size_t)i * DIM);
        float s = 0.0f, mx = 0.0f, l1 = 0.0f;
        #pragma unroll 8
        for (int j = 0; j < DIM / 4; j++) {
            float4 v = row[j];
            s = __fadd_rn(s, __fmul_rn(v.x, v.x));
            s = __fadd_rn(s, __fmul_rn(v.y, v.y));
            s = __fadd_rn(s, __fmul_rn(v.z, v.z));
            s = __fadd_rn(s, __fmul_rn(v.w, v.w));
            float ax = fabsf(v.x), ay = fabsf(v.y), az = fabsf(v.z), aw = fabsf(v.w);
            mx = fmaxf(fmaxf(mx, ax), fmaxf(ay, fmaxf(az, aw)));
            l1 += ax + ay + az + aw;
        }
        g_S[i] = s;
        mx = fmaxf(mx, 1e-30f);
        float inv = 127.0f / mx;
        g_sx[i] = mx / 127.0f;
        g_Lx[i] = l1;
        #pragma unroll 8
        for (int k = 0; k < NKCH; k++) {
            float4 v = row[k];
            int q0 = q8(v.x, inv), q1 = q8(v.y, inv), q2 = q8(v.z, inv), q3 = q8(v.w, inv);
            g_XqT[k * N_TOK + i] = (q0 & 255) | ((q1 & 255) << 8) | ((q2 & 255) << 16) | ((q3 & 255) << 24);
        }
    }
    if (i < KCB) {
        const float4* row = reinterpret_cast<const float4*>(E + (size_t)i * DIM);
        float s = 0.0f, mx = 0.0f, l1 = 0.0f;
        #pragma unroll 8
        for (int j = 0; j < DIM / 4; j++) {
            float4 v = row[j];
            s = __fadd_rn(s, __fmul_rn(v.x, v.x));
            s = __fadd_rn(s, __fmul_rn(v.y, v.y));
            s = __fadd_rn(s, __fmul_rn(v.z, v.z));
            s = __fadd_rn(s, __fmul_rn(v.w, v.w));
            float ax = fabsf(v.x), ay = fabsf(v.y), az = fabsf(v.z), aw = fabsf(v.w);
            mx = fmaxf(fmaxf(mx, ax), fmaxf(ay, fmaxf(az, aw)));
            l1 += ax + ay + az + aw;
        }
        g_c[i] = s;
        mx = fmaxf(mx, 1e-30f);
        float inv = 127.0f / mx;
        g_se[i] = mx / 127.0f;
        g_Le[i] = l1;
        #pragma unroll 8
        for (int k = 0; k < NKCH; k++) {
            float4 v = row[k];
            int q0 = q8(v.x, inv), q1 = q8(v.y, inv), q2 = q8(v.z, inv), q3 = q8(v.w, inv);
            g_EqT[k * KCB + i] = (q0 & 255) | ((q1 & 255) << 8) | ((q2 & 255) << 16) | ((q3 & 255) << 24);
        }
    }
}

// ---------------------------------------------------------------------------
// Kernel 2: global max of se / Le over codes (for rigorous per-token margins).
// ---------------------------------------------------------------------------
__global__ void reduce_kernel() {
    __shared__ float s1[256], s2[256];
    float m1 = 0.0f, m2 = 0.0f;
    for (int j = threadIdx.x; j < KCB; j += 256) {
        m1 = fmaxf(m1, g_se[j]);
        m2 = fmaxf(m2, g_Le[j]);
    }
    s1[threadIdx.x] = m1; s2[threadIdx.x] = m2;
    __syncthreads();
    for (int off = 128; off >= 1; off >>= 1) {
        if (threadIdx.x < off) {
            s1[threadIdx.x] = fmaxf(s1[threadIdx.x], s1[threadIdx.x + off]);
            s2[threadIdx.x] = fmaxf(s2[threadIdx.x], s2[threadIdx.x + off]);
        }
        __syncthreads();
    }
    if (threadIdx.x == 0) { g_maxse = s1[0]; g_maxLe = s2[0]; }
}

// ---------------------------------------------------------------------------
// Kernel 3: int8 dp4a coarse GEMM + margin candidate collection.
// CTA = 128 tokens x 4096 codes (32 tiles of 128). 256 threads as 16(ty)x16(tx),
// 8 tokens x 8 codes per thread, exact int32 dots. Token-global running min
// via half-warp shfl. Candidates (code, coarse score) stored; expected appends
// ~48/token (running-min-relative), MAX_CAND=128 makes overflow negligible.
// ---------------------------------------------------------------------------
#define SM_X    0                     // int Xs[64][128]            32KB
#define SM_E    32768                 // int Es[2][64][128]         64KB
#define SM_MARG 98304                 // float marg[128]
#define SM_SX   98816                 // float sx[128]
#define SMEM_TOTAL 99328

__global__ __launch_bounds__(256) void coarse_kernel() {
    extern __shared__ __align__(16) char smem[];
    const int tid = threadIdx.x;
    const int tx = tid & 15, ty = tid >> 4;
    const int mb = blockIdx.x * TOK_TILE;
    uint32_t sb = smem_to_u32(smem);
    int* Xs = reinterpret_cast<int*>(smem + SM_X);
    int* Es = reinterpret_cast<int*>(smem + SM_E);
    float* marg_s = reinterpret_cast<float*>(smem + SM_MARG);
    float* sx_s = reinterpret_cast<float*>(smem + SM_SX);

    if (tid < TOK_TILE) {
        float sx = g_sx[mb + tid];
        float lx = g_Lx[mb + tid];
        sx_s[tid] = sx;
        marg_s[tid] = token_margin(sx, lx, g_maxse, g_maxLe);
    }

    // X tile: 64 kchunks x 128 tokens (cp.async, contiguous 512B rows)
    #pragma unroll
    for (int k = 0; k < 8; k++) {
        int v = tid + k * 256;
        int row = v >> 5, ch = v & 31;
        cp_async16(sb + SM_X + (row * 128 + ch * 4) * 4,
                   g_XqT + (size_t)row * N_TOK + mb + ch * 4);
    }
    // E tile 0
    #pragma unroll
    for (int k = 0; k < 8; k++) {
        int v = tid + k * 256;
        int row = v >> 5, ch = v & 31;
        cp_async16(sb + SM_E + (row * 128 + ch * 4) * 4,
                   g_EqT + (size_t)row * KCB + ch * 4);
    }
    cp_commit();
    cp_wait0();
    __syncthreads();

    float sxv[8], margv[8], runmin[8];
    #pragma unroll
    for (int i = 0; i < 8; i++) {
        sxv[i]   = sx_s[ty * 8 + i];
        margv[i] = marg_s[ty * 8 + i];
        runmin[i] = CUDART_INF_F;
    }

    for (int ct = 0; ct < N_CTILE; ct++) {
        const int cur = ct & 1;

        if (ct < N_CTILE - 1) {
            #pragma unroll
            for (int k = 0; k < 8; k++) {
                int v = tid + k * 256;
                int row = v >> 5, ch = v & 31;
                cp_async16(sb + SM_E + ((cur ^ 1) * 8192 + row * 128 + ch * 4) * 4,
                           g_EqT + (size_t)row * KCB + (ct + 1) * CODE_TILE + ch * 4);
            }
            cp_commit();
        }

        int acc[8][8];
        #pragma unroll
        for (int i = 0; i < 8; i++)
            #pragma unroll
            for (int j = 0; j < 8; j++) acc[i][j] = 0;

        const int* eb = Es + cur * 8192;
        #pragma unroll 4
        for (int kc = 0; kc < NKCH; kc++) {
            int4 a0 = *reinterpret_cast<const int4*>(Xs + kc * 128 + ty * 8);
            int4 a1 = *reinterpret_cast<const int4*>(Xs + kc * 128 + ty * 8 + 4);
            int4 b0 = *reinterpret_cast<const int4*>(eb + kc * 128 + tx * 8);
            int4 b1 = *reinterpret_cast<const int4*>(eb + kc * 128 + tx * 8 + 4);
            int aw[8] = {a0.x, a0.y, a0.z, a0.w, a1.x, a1.y, a1.z, a1.w};
            int bw[8] = {b0.x, b0.y, b0.z, b0.w, b1.x, b1.y, b1.z, b1.w};
            #pragma unroll
            for (int i = 0; i < 8; i++)
                #pragma unroll
                for (int j = 0; j < 8; j++)
                    dp4a(acc[i][j], aw[i], bw[j]);
        }

        // epilogue: s_hat, half-warp tile-min reduce, running-min collection
        float se8[8], c8[8];
        #pragma unroll
        for (int j = 0; j < 8; j++) {
            int code = ct * CODE_TILE + tx * 8 + j;
            se8[j] = __ldg(&g_se[code]);
            c8[j]  = __ldg(&g_c[code]);
        }
        #pragma unroll
        for (int i = 0; i < 8; i++) {
            const float nsx = -2.0f * sxv[i];
            float s[8];
            float tmin = CUDART_INF_F;
            #pragma unroll
            for (int j = 0; j < 8; j++) {
                s[j] = fmaf(nsx * se8[j], (float)acc[i][j], c8[j]);
                tmin = fminf(tmin, s[j]);
            }
            // reduce tile-min across the 16 code-lanes (same half-warp)
            #pragma unroll
            for (int off = 8; off >= 1; off >>= 1)
                tmin = fminf(tmin, __shfl_xor_sync(0xffffffffu, tmin, off));
            runmin[i] = fminf(runmin[i], tmin);
            const float th = runmin[i] + margv[i];
            bool any = false;
            #pragma unroll
            for (int j = 0; j < 8; j++) any |= (s[j] <= th);
            if (any) {
                const int token = mb + ty * 8 + i;
                #pragma unroll
                for (int j = 0; j < 8; j++) {
                    if (s[j] <= th) {
                        int code = ct * CODE_TILE + tx * 8 + j;
                        int p = atomicAdd(&g_ncand[token], 1);
                        if (p < MAX_CAND) {
                            g_cand[token][p] = (unsigned short)code;
                            g_cand_s[token][p] = s[j];
                        }
                    }
                }
            }
        }

        if (ct < N_CTILE - 1) cp_wait0();
        __syncthreads();
    }
}

// ---------------------------------------------------------------------------
// Kernel 4: survivor-filtered exact rescore + gather + STE output + loss.
// One warp per token; up to 4 candidate slots per lane (MAX_CAND=128).
//  - survivors = candidates with coarse s <= finalmin + marg (provably
//    contains the exact argmin and all exact ties).
//  - 1 survivor  -> it IS the argmin; no dot products.
//  - >1 survivor -> exact R2-chain d2 on surviving slots, lexicographic min.
//  - overflow (n > MAX_CAND, ~never) -> exact full scan.
// ---------------------------------------------------------------------------
__global__ void rescore_output_kernel(const float* __restrict__ X, const float* __restrict__ E,
                                      float* __restrict__ out_q, float* __restrict__ out_idx_f) {
    int token = (blockIdx.x * blockDim.x + threadIdx.x) >> 5;
    int lane = threadIdx.x & 31;
    if (token >= N_TOK) return;
    int n = g_ncand[token];
    float S = g_S[token];
    const float4* xr = reinterpret_cast<const float4*>(X + (size_t)token * DIM);

    int besti = 0x7fffffff;

    if (n <= MAX_CAND) {
        float sc[4];
        int   cd[4];
        #pragma unroll
        for (int q = 0; q < 4; q++) {
            int idx = lane + q * 32;
            if (idx < n) { cd[q] = g_cand[token][idx]; sc[q] = g_cand_s[token][idx]; }
            else         { cd[q] = 0x7fffffff;         sc[q] = CUDART_INF_F; }
        }
        float fm = fminf(fminf(sc[0], sc[1]), fminf(sc[2], sc[3]));
        #pragma unroll
        for (int off = 16; off >= 1; off >>= 1)
            fm = fminf(fm, __shfl_xor_sync(0xffffffffu, fm, off));
        const float marg = token_margin(g_sx[token], g_Lx[token], g_maxse, g_maxLe);
        const float th = fm + marg;

        bool sv[4];
        int tot = 0;
        #pragma unroll
        for (int q = 0; q < 4; q++) {
            sv[q] = (sc[q] <= th);
            tot += __popc(__ballot_sync(0xffffffffu, sv[q]));
        }

        if (tot == 1) {
            int myc = 0x7fffffff;
            #pragma unroll
            for (int q = 0; q < 4; q++) if (sv[q]) myc = cd[q];
            #pragma unroll
            for (int off = 16; off >= 1; off >>= 1)
                myc = min(myc, __shfl_xor_sync(0xffffffffu, myc, off));
            besti = myc;
        } else {
            float bestv = CUDART_INF_F;
            #pragma unroll
            for (int q = 0; q < 4; q++) {
                if (sv[q]) {
                    const float4* er = reinterpret_cast<const float4*>(E + (size_t)cd[q] * DIM);
                    float m = 0.0f;
                    #pragma unroll 8
                    for (int k = 0; k < DIM / 4; k++) {
                        float4 x = xr[k], e = er[k];
                        m = fmaf(x.x, e.x, m); m = fmaf(x.y, e.y, m);
                        m = fmaf(x.z, e.z, m); m = fmaf(x.w, e.w, m);
                    }
                    float t = fmaf(-2.0f, m, S);
                    float d2 = __fadd_rn(t, g_c[cd[q]]);
                    if (d2 < bestv || (d2 == bestv && cd[q] < besti)) { bestv = d2; besti = cd[q]; }
                }
            }
            #pragma unroll
            for (int off = 16; off >= 1; off >>= 1) {
                float ov = __shfl_xor_sync(0xffffffffu, bestv, off);
                int   oi = __shfl_xor_sync(0xffffffffu, besti, off);
                if (ov < bestv || (ov == bestv && oi < besti)) { bestv = ov; besti = oi; }
            }
            besti = __shfl_sync(0xffffffffu, besti, 0);
        }
    } else {
        // overflow fallback: exact scan of all codes (probability ~0)
        float bestv = CUDART_INF_F;
        for (int code = lane; code < KCB; code += 32) {
            const float4* er = reinterpret_cast<const float4*>(E + (size_t)code * DIM);
            float m = 0.0f;
            #pragma unroll 8
            for (int k = 0; k < DIM / 4; k++) {
                float4 x = xr[k], e = er[k];
                m = fmaf(x.x, e.x, m); m = fmaf(x.y, e.y, m);
                m = fmaf(x.z, e.z, m); m = fmaf(x.w, e.w, m);
            }
            float t = fmaf(-2.0f, m, S);
            float d2 = __fadd_rn(t, g_c[code]);
            if (d2 < bestv || (d2 == bestv && code < besti)) { bestv = d2; besti = code; }
        }
        #pragma unroll
        for (int off = 16; off >= 1; off >>= 1) {
            float ov = __shfl_xor_sync(0xffffffffu, bestv, off);
            int   oi = __shfl_xor_sync(0xffffffffu, besti, off);
            if (ov < bestv || (ov == bestv && oi < besti)) { bestv = ov; besti = oi; }
        }
        besti = __shfl_sync(0xffffffffu, besti, 0);
    }

    // gather + straight-through + loss (bit-exact R2 arithmetic)
    const float4* er = reinterpret_cast<const float4*>(E + (size_t)besti * DIM);
    float* qr = out_q + (size_t)token * DIM;   // 4B-aligned only -> scalar stores
    float ls = 0.0f;
    #pragma unroll
    for (int j = lane; j < DIM / 4; j += 32) {
        float4 x = xr[j], e = er[j];
        float4 d, o;
        d.x = __fadd_rn(e.x, -x.x); d.y = __fadd_rn(e.y, -x.y);
        d.z = __fadd_rn(e.z, -x.z); d.w = __fadd_rn(e.w, -x.w);
        ls = __fadd_rn(ls, __fmul_rn(d.x, d.x));
        ls = __fadd_rn(ls, __fmul_rn(d.y, d.y));
        ls = __fadd_rn(ls, __fmul_rn(d.z, d.z));
        ls = __fadd_rn(ls, __fmul_rn(d.w, d.w));
        o.x = __fadd_rn(x.x, d.x); o.y = __fadd_rn(x.y, d.y);
        o.z = __fadd_rn(x.z, d.z); o.w = __fadd_rn(x.w, d.w);
        qr[j * 4 + 0] = o.x;
        qr[j * 4 + 1] = o.y;
        qr[j * 4 + 2] = o.z;
        qr[j * 4 + 3] = o.w;
    }
    #pragma unroll
    for (int off = 16; off >= 1; off >>= 1)
        ls = __fadd_rn(ls, __shfl_xor_sync(0xffffffffu, ls, off));
    if (lane == 0) {
        g_loss[token] = ls;
        out_idx_f[token] = (float)besti;
    }
}

// ---------------------------------------------------------------------------
// Kernels 5+6: two-stage deterministic double-precision loss reduction.
// ---------------------------------------------------------------------------
__global__ void finalize1_kernel() {
    __shared__ double sh[256];
    int b = blockIdx.x;
    sh[threadIdx.x] = (double)g_loss[b * 256 + threadIdx.x];
    __syncthreads();
    for (int off = 128; off >= 1; off >>= 1) {
        if (threadIdx.x < off) sh[threadIdx.x] += sh[threadIdx.x + off];
        __syncthreads();
    }
    if (threadIdx.x == 0) g_part[b] = sh[0];
}
__global__ void finalize2_kernel(float* __restrict__ out) {
    __shared__ double sh[128];
    sh[threadIdx.x] = g_part[threadIdx.x];
    __syncthreads();
    for (int off = 64; off >= 1; off >>= 1) {
        if (threadIdx.x < off) sh[threadIdx.x] += sh[threadIdx.x + off];
        __syncthreads();
    }
    if (threadIdx.x == 0)
        out[0] = (float)(0.5 * sh[0] / ((double)N_TOK * (double)DIM));
}

// ---------------------------------------------------------------------------
extern "C" void kernel_launch(void* const* d_in, const int* in_sizes, int n_in,
                              void* d_out, int out_size) {
    const float* X = (const float*)d_in[0];   // embedding_tokens [N, D]
    const float* E = (const float*)d_in[1];   // embeddings       [K, D]
    float* out = (float*)d_out;
    float* out_q   = out + 1;
    float* out_idx = out + 1 + (size_t)N_TOK * DIM;

    static int smem_set = 0;
    if (!smem_set) {
        cudaFuncSetAttribute(coarse_kernel, cudaFuncAttributeMaxDynamicSharedMemorySize, SMEM_TOTAL);
        smem_set = 1;
    }

    prep_kernel<<<N_TOK / 256, 256>>>(X, E);
    reduce_kernel<<<1, 256>>>();
    coarse_kernel<<<N_TOK / TOK_TILE, 256, SMEM_TOTAL>>>();
    rescore_output_kernel<<<(N_TOK * 32) / 256, 256>>>(X, E, out_q, out_idx);
    finalize1_kernel<<<128, 256>>>();
    finalize2_kernel<<<1, 128>>>(out);
}

// round 11
// speedup vs baseline: 2.0238x; 1.0015x over previous
#include <cuda_runtime.h>
#include <math_constants.h>
#include <cstdint>

// Problem constants: B=16,T=2048,D=256,K=4096
#define N_TOK 32768
#define DIM   256
#define KCB   4096
#define NKCH  (DIM / 4)     // 64 packed int32 k-chunks per row

#define TOK_TILE  128
#define CODE_TILE 128
#define N_QUART   4                        // code-range quarters per token tile
#define QRANGE    (KCB / N_QUART)          // 1024 codes per CTA
#define N_CTILE   (QRANGE / CODE_TILE)     // 8 tiles per CTA
#define MAX_CAND  192

// ---------------- device scratch (no allocations allowed) -------------------
__device__ float  g_S[N_TOK];
__device__ float  g_c[KCB];
__device__ float  g_loss[N_TOK];
__device__ double g_part[128];
__device__ float  g_sx[N_TOK], g_Lx[N_TOK];
__device__ float  g_se[KCB],  g_Le[KCB];
__device__ float  g_maxse, g_maxLe;
__device__ __align__(16) int g_XqT[NKCH * N_TOK];   // [kchunk][token]  8MB
__device__ __align__(16) int g_EqT[NKCH * KCB];     // [kchunk][code]   1MB
__device__ unsigned short g_cand[N_TOK][MAX_CAND];  // 12MB
__device__ float  g_cand_s[N_TOK][MAX_CAND];        // 24MB coarse scores
__device__ int    g_ncand[N_TOK];

// ---------------- helpers ----------------------------------------------------
__device__ __forceinline__ uint32_t smem_to_u32(const void* p) {
    uint32_t a;
    asm("{ .reg .u64 t; cvta.to.shared.u64 t, %1; cvt.u32.u64 %0, t; }" : "=r"(a) : "l"(p));
    return a;
}
__device__ __forceinline__ void dp4a(int& acc, int a, int b) {
    asm("dp4a.s32.s32 %0, %1, %2, %0;" : "+r"(acc) : "r"(a), "r"(b));
}
__device__ __forceinline__ void cp_async16(uint32_t dst_smem, const void* src) {
    asm volatile("cp.async.cg.shared.global [%0], [%1], 16;" :: "r"(dst_smem), "l"(src) : "memory");
}
__device__ __forceinline__ void cp_commit() { asm volatile("cp.async.commit_group;" ::: "memory"); }
__device__ __forceinline__ void cp_wait0()  { asm volatile("cp.async.wait_group 0;"  ::: "memory"); }
__device__ __forceinline__ int q8(float v, float inv) {
    int q = __float2int_rn(v * inv);
    return max(-127, min(127, q));
}
// rigorous per-token margin: 2*(int8 quant bound on 2m) + fp32 d2-chain slop
__device__ __forceinline__ float token_margin(float sx, float lx, float mse, float mle) {
    return 2.0f * (0.5f * sx * mle + 0.5f * mse * lx + 128.0f * sx * mse) + 3.0e-4f;
}

// ---------------------------------------------------------------------------
// Kernel 1: per-row exact-fp32 sums of squares (bit-matching R2 chain),
// per-row max/L1, int8 quantization into TRANSPOSED packed layout.
// ---------------------------------------------------------------------------
__global__ void prep_kernel(const float* __restrict__ X, const float* __restrict__ E) {
    int i = blockIdx.x * blockDim.x + threadIdx.x;
    if (i < N_TOK) {
        g_ncand[i] = 0;
        const float4* row = reinterpret_cast<const float4*>(X + (size_t)i * DIM);
        float s = 0.0f, mx = 0.0f, l1 = 0.0f;
        #pragma unroll 8
        for (int j = 0; j < DIM / 4; j++) {
            float4 v = row[j];
            s = __fadd_rn(s, __fmul_rn(v.x, v.x));
            s = __fadd_rn(s, __fmul_rn(v.y, v.y));
            s = __fadd_rn(s, __fmul_rn(v.z, v.z));
            s = __fadd_rn(s, __fmul_rn(v.w, v.w));
            float ax = fabsf(v.x), ay = fabsf(v.y), az = fabsf(v.z), aw = fabsf(v.w);
            mx = fmaxf(fmaxf(mx, ax), fmaxf(ay, fmaxf(az, aw)));
            l1 += ax + ay + az + aw;
        }
        g_S[i] = s;
        mx = fmaxf(mx, 1e-30f);
        float inv = 127.0f / mx;
        g_sx[i] = mx / 127.0f;
        g_Lx[i] = l1;
        #pragma unroll 8
        for (int k = 0; k < NKCH; k++) {
            float4 v = row[k];
            int q0 = q8(v.x, inv), q1 = q8(v.y, inv), q2 = q8(v.z, inv), q3 = q8(v.w, inv);
            g_XqT[k * N_TOK + i] = (q0 & 255) | ((q1 & 255) << 8) | ((q2 & 255) << 16) | ((q3 & 255) << 24);
        }
    }
    if (i < KCB) {
        const float4* row = reinterpret_cast<const float4*>(E + (size_t)i * DIM);
        float s = 0.0f, mx = 0.0f, l1 = 0.0f;
        #pragma unroll 8
        for (int j = 0; j < DIM / 4; j++) {
            float4 v = row[j];
            s = __fadd_rn(s, __fmul_rn(v.x, v.x));
            s = __fadd_rn(s, __fmul_rn(v.y, v.y));
            s = __fadd_rn(s, __fmul_rn(v.z, v.z));
            s = __fadd_rn(s, __fmul_rn(v.w, v.w));
            float ax = fabsf(v.x), ay = fabsf(v.y), az = fabsf(v.z), aw = fabsf(v.w);
            mx = fmaxf(fmaxf(mx, ax), fmaxf(ay, fmaxf(az, aw)));
            l1 += ax + ay + az + aw;
        }
        g_c[i] = s;
        mx = fmaxf(mx, 1e-30f);
        float inv = 127.0f / mx;
        g_se[i] = mx / 127.0f;
        g_Le[i] = l1;
        #pragma unroll 8
        for (int k = 0; k < NKCH; k++) {
            float4 v = row[k];
            int q0 = q8(v.x, inv), q1 = q8(v.y, inv), q2 = q8(v.z, inv), q3 = q8(v.w, inv);
            g_EqT[k * KCB + i] = (q0 & 255) | ((q1 & 255) << 8) | ((q2 & 255) << 16) | ((q3 & 255) << 24);
        }
    }
}

// ---------------------------------------------------------------------------
// Kernel 2: global max of se / Le over codes (for rigorous per-token margins).
// ---------------------------------------------------------------------------
__global__ void reduce_kernel() {
    __shared__ float s1[256], s2[256];
    float m1 = 0.0f, m2 = 0.0f;
    for (int j = threadIdx.x; j < KCB; j += 256) {
        m1 = fmaxf(m1, g_se[j]);
        m2 = fmaxf(m2, g_Le[j]);
    }
    s1[threadIdx.x] = m1; s2[threadIdx.x] = m2;
    __syncthreads();
    for (int off = 128; off >= 1; off >>= 1) {
        if (threadIdx.x < off) {
            s1[threadIdx.x] = fmaxf(s1[threadIdx.x], s1[threadIdx.x + off]);
            s2[threadIdx.x] = fmaxf(s2[threadIdx.x], s2[threadIdx.x + off]);
        }
        __syncthreads();
    }
    if (threadIdx.x == 0) { g_maxse = s1[0]; g_maxLe = s2[0]; }
}

// ---------------------------------------------------------------------------
// Kernel 3: int8 dp4a coarse GEMM + margin candidate collection.
// Grid = 256 token-tiles x 4 code-quarters = 1024 CTAs (~69us each) so the
// HW scheduler can balance 2-CTA/SM slots (fixes the 108/40 wave imbalance
// of the 256-CTA version). Each CTA: 128 tokens x 1024 codes, local runmin
// per token over its quarter (conservative => still a provable superset).
// 256 threads as 16(ty)x16(tx), 8x8 microtile, exact int32 dots.
// ---------------------------------------------------------------------------
#define SM_X    0                     // int Xs[64][128]            32KB
#define SM_E    32768                 // int Es[2][64][128]         64KB
#define SM_MARG 98304                 // float marg[128]
#define SM_SX   98816                 // float sx[128]
#define SMEM_TOTAL 99328

__global__ __launch_bounds__(256) void coarse_kernel() {
    extern __shared__ __align__(16) char smem[];
    const int tid = threadIdx.x;
    const int tx = tid & 15, ty = tid >> 4;
    const int mb = (blockIdx.x >> 2) * TOK_TILE;       // token base
    const int cq = (blockIdx.x & 3) * QRANGE;          // code-quarter base
    uint32_t sb = smem_to_u32(smem);
    int* Xs = reinterpret_cast<int*>(smem + SM_X);
    int* Es = reinterpret_cast<int*>(smem + SM_E);
    float* marg_s = reinterpret_cast<float*>(smem + SM_MARG);
    float* sx_s = reinterpret_cast<float*>(smem + SM_SX);

    if (tid < TOK_TILE) {
        float sx = g_sx[mb + tid];
        float lx = g_Lx[mb + tid];
        sx_s[tid] = sx;
        marg_s[tid] = token_margin(sx, lx, g_maxse, g_maxLe);
    }

    // X tile: 64 kchunks x 128 tokens (cp.async, contiguous 512B rows)
    #pragma unroll
    for (int k = 0; k < 8; k++) {
        int v = tid + k * 256;
        int row = v >> 5, ch = v & 31;
        cp_async16(sb + SM_X + (row * 128 + ch * 4) * 4,
                   g_XqT + (size_t)row * N_TOK + mb + ch * 4);
    }
    // E tile 0 of this quarter
    #pragma unroll
    for (int k = 0; k < 8; k++) {
        int v = tid + k * 256;
        int row = v >> 5, ch = v & 31;
        cp_async16(sb + SM_E + (row * 128 + ch * 4) * 4,
                   g_EqT + (size_t)row * KCB + cq + ch * 4);
    }
    cp_commit();
    cp_wait0();
    __syncthreads();

    float sxv[8], margv[8], runmin[8];
    #pragma unroll
    for (int i = 0; i < 8; i++) {
        sxv[i]   = sx_s[ty * 8 + i];
        margv[i] = marg_s[ty * 8 + i];
        runmin[i] = CUDART_INF_F;
    }

    for (int ct = 0; ct < N_CTILE; ct++) {
        const int cur = ct & 1;

        if (ct < N_CTILE - 1) {
            #pragma unroll
            for (int k = 0; k < 8; k++) {
                int v = tid + k * 256;
                int row = v >> 5, ch = v & 31;
                cp_async16(sb + SM_E + ((cur ^ 1) * 8192 + row * 128 + ch * 4) * 4,
                           g_EqT + (size_t)row * KCB + cq + (ct + 1) * CODE_TILE + ch * 4);
            }
            cp_commit();
        }

        int acc[8][8];
        #pragma unroll
        for (int i = 0; i < 8; i++)
            #pragma unroll
            for (int j = 0; j < 8; j++) acc[i][j] = 0;

        const int* eb = Es + cur * 8192;
        #pragma unroll 4
        for (int kc = 0; kc < NKCH; kc++) {
            int4 a0 = *reinterpret_cast<const int4*>(Xs + kc * 128 + ty * 8);
            int4 a1 = *reinterpret_cast<const int4*>(Xs + kc * 128 + ty * 8 + 4);
            int4 b0 = *reinterpret_cast<const int4*>(eb + kc * 128 + tx * 8);
            int4 b1 = *reinterpret_cast<const int4*>(eb + kc * 128 + tx * 8 + 4);
            int aw[8] = {a0.x, a0.y, a0.z, a0.w, a1.x, a1.y, a1.z, a1.w};
            int bw[8] = {b0.x, b0.y, b0.z, b0.w, b1.x, b1.y, b1.z, b1.w};
            #pragma unroll
            for (int i = 0; i < 8; i++)
                #pragma unroll
                for (int j = 0; j < 8; j++)
                    dp4a(acc[i][j], aw[i], bw[j]);
        }

        // epilogue: s_hat, half-warp tile-min reduce, running-min collection
        float se8[8], c8[8];
        #pragma unroll
        for (int j = 0; j < 8; j++) {
            int code = cq + ct * CODE_TILE + tx * 8 + j;
            se8[j] = __ldg(&g_se[code]);
            c8[j]  = __ldg(&g_c[code]);
        }
        #pragma unroll
        for (int i = 0; i < 8; i++) {
            const float nsx = -2.0f * sxv[i];
            float s[8];
            float tmin = CUDART_INF_F;
            #pragma unroll
            for (int j = 0; j < 8; j++) {
                s[j] = fmaf(nsx * se8[j], (float)acc[i][j], c8[j]);
                tmin = fminf(tmin, s[j]);
            }
            // reduce tile-min across the 16 code-lanes (same half-warp)
            #pragma unroll
            for (int off = 8; off >= 1; off >>= 1)
                tmin = fminf(tmin, __shfl_xor_sync(0xffffffffu, tmin, off));
            runmin[i] = fminf(runmin[i], tmin);
            const float th = runmin[i] + margv[i];
            bool any = false;
            #pragma unroll
            for (int j = 0; j < 8; j++) any |= (s[j] <= th);
            if (any) {
                const int token = mb + ty * 8 + i;
                #pragma unroll
                for (int j = 0; j < 8; j++) {
                    if (s[j] <= th) {
                        int code = cq + ct * CODE_TILE + tx * 8 + j;
                        int p = atomicAdd(&g_ncand[token], 1);
                        if (p < MAX_CAND) {
                            g_cand[token][p] = (unsigned short)code;
                            g_cand_s[token][p] = s[j];
                        }
                    }
                }
            }
        }

        if (ct < N_CTILE - 1) cp_wait0();
        __syncthreads();
    }
}

// ---------------------------------------------------------------------------
// Kernel 4: survivor-filtered exact rescore + gather + STE output + loss.
// One warp per token; up to 6 candidate slots per lane (MAX_CAND=192).
//  - survivors = candidates with coarse s <= global finalmin + marg (provably
//    contains the exact argmin and all exact ties).
//  - 1 survivor  -> it IS the argmin; no dot products.
//  - >1 survivor -> exact R2-chain d2 on surviving slots, lexicographic min.
//  - overflow (n > MAX_CAND, ~never) -> exact full scan (also exact).
// ---------------------------------------------------------------------------
#define NSLOT (MAX_CAND / 32)   // 6

__global__ void rescore_output_kernel(const float* __restrict__ X, const float* __restrict__ E,
                                      float* __restrict__ out_q, float* __restrict__ out_idx_f) {
    int token = (blockIdx.x * blockDim.x + threadIdx.x) >> 5;
    int lane = threadIdx.x & 31;
    if (token >= N_TOK) return;
    int n = g_ncand[token];
    float S = g_S[token];
    const float4* xr = reinterpret_cast<const float4*>(X + (size_t)token * DIM);

    int besti = 0x7fffffff;

    if (n <= MAX_CAND) {
        float sc[NSLOT];
        int   cd[NSLOT];
        #pragma unroll
        for (int q = 0; q < NSLOT; q++) {
            int idx = lane + q * 32;
            if (idx < n) { cd[q] = g_cand[token][idx]; sc[q] = g_cand_s[token][idx]; }
            else         { cd[q] = 0x7fffffff;         sc[q] = CUDART_INF_F; }
        }
        float fm = CUDART_INF_F;
        #pragma unroll
        for (int q = 0; q < NSLOT; q++) fm = fminf(fm, sc[q]);
        #pragma unroll
        for (int off = 16; off >= 1; off >>= 1)
            fm = fminf(fm, __shfl_xor_sync(0xffffffffu, fm, off));
        const float marg = token_margin(g_sx[token], g_Lx[token], g_maxse, g_maxLe);
        const float th = fm + marg;

        bool sv[NSLOT];
        int tot = 0;
        #pragma unroll
        for (int q = 0; q < NSLOT; q++) {
            sv[q] = (sc[q] <= th);
            tot += __popc(__ballot_sync(0xffffffffu, sv[q]));
        }

        if (tot == 1) {
            int myc = 0x7fffffff;
            #pragma unroll
            for (int q = 0; q < NSLOT; q++) if (sv[q]) myc = cd[q];
            #pragma unroll
            for (int off = 16; off >= 1; off >>= 1)
                myc = min(myc, __shfl_xor_sync(0xffffffffu, myc, off));
            besti = myc;
        } else {
            float bestv = CUDART_INF_F;
            #pragma unroll
            for (int q = 0; q < NSLOT; q++) {
                if (sv[q]) {
                    const float4* er = reinterpret_cast<const float4*>(E + (size_t)cd[q] * DIM);
                    float m = 0.0f;
                    #pragma unroll 8
                    for (int k = 0; k < DIM / 4; k++) {
                        float4 x = xr[k], e = er[k];
                        m = fmaf(x.x, e.x, m); m = fmaf(x.y, e.y, m);
                        m = fmaf(x.z, e.z, m); m = fmaf(x.w, e.w, m);
                    }
                    float t = fmaf(-2.0f, m, S);
                    float d2 = __fadd_rn(t, g_c[cd[q]]);
                    if (d2 < bestv || (d2 == bestv && cd[q] < besti)) { bestv = d2; besti = cd[q]; }
                }
            }
            #pragma unroll
            for (int off = 16; off >= 1; off >>= 1) {
                float ov = __shfl_xor_sync(0xffffffffu, bestv, off);
                int   oi = __shfl_xor_sync(0xffffffffu, besti, off);
                if (ov < bestv || (ov == bestv && oi < besti)) { bestv = ov; besti = oi; }
            }
            besti = __shfl_sync(0xffffffffu, besti, 0);
        }
    } else {
        // overflow fallback: exact scan of all codes (probability ~0)
        float bestv = CUDART_INF_F;
        for (int code = lane; code < KCB; code += 32) {
            const float4* er = reinterpret_cast<const float4*>(E + (size_t)code * DIM);
            float m = 0.0f;
            #pragma unroll 8
            for (int k = 0; k < DIM / 4; k++) {
                float4 x = xr[k], e = er[k];
                m = fmaf(x.x, e.x, m); m = fmaf(x.y, e.y, m);
                m = fmaf(x.z, e.z, m); m = fmaf(x.w, e.w, m);
            }
            float t = fmaf(-2.0f, m, S);
            float d2 = __fadd_rn(t, g_c[code]);
            if (d2 < bestv || (d2 == bestv && code < besti)) { bestv = d2; besti = code; }
        }
        #pragma unroll
        for (int off = 16; off >= 1; off >>= 1) {
            float ov = __shfl_xor_sync(0xffffffffu, bestv, off);
            int   oi = __shfl_xor_sync(0xffffffffu, besti, off);
            if (ov < bestv || (ov == bestv && oi < besti)) { bestv = ov; besti = oi; }
        }
        besti = __shfl_sync(0xffffffffu, besti, 0);
    }

    // gather + straight-through + loss (bit-exact R2 arithmetic)
    const float4* er = reinterpret_cast<const float4*>(E + (size_t)besti * DIM);
    float* qr = out_q + (size_t)token * DIM;   // 4B-aligned only -> scalar stores
    float ls = 0.0f;
    #pragma unroll
    for (int j = lane; j < DIM / 4; j += 32) {
        float4 x = xr[j], e = er[j];
        float4 d, o;
        d.x = __fadd_rn(e.x, -x.x); d.y = __fadd_rn(e.y, -x.y);
        d.z = __fadd_rn(e.z, -x.z); d.w = __fadd_rn(e.w, -x.w);
        ls = __fadd_rn(ls, __fmul_rn(d.x, d.x));
        ls = __fadd_rn(ls, __fmul_rn(d.y, d.y));
        ls = __fadd_rn(ls, __fmul_rn(d.z, d.z));
        ls = __fadd_rn(ls, __fmul_rn(d.w, d.w));
        o.x = __fadd_rn(x.x, d.x); o.y = __fadd_rn(x.y, d.y);
        o.z = __fadd_rn(x.z, d.z); o.w = __fadd_rn(x.w, d.w);
        qr[j * 4 + 0] = o.x;
        qr[j * 4 + 1] = o.y;
        qr[j * 4 + 2] = o.z;
        qr[j * 4 + 3] = o.w;
    }
    #pragma unroll
    for (int off = 16; off >= 1; off >>= 1)
        ls = __fadd_rn(ls, __shfl_xor_sync(0xffffffffu, ls, off));
    if (lane == 0) {
        g_loss[token] = ls;
        out_idx_f[token] = (float)besti;
    }
}

// ---------------------------------------------------------------------------
// Kernels 5+6: two-stage deterministic double-precision loss reduction.
// ---------------------------------------------------------------------------
__global__ void finalize1_kernel() {
    __shared__ double sh[256];
    int b = blockIdx.x;
    sh[threadIdx.x] = (double)g_loss[b * 256 + threadIdx.x];
    __syncthreads();
    for (int off = 128; off >= 1; off >>= 1) {
        if (threadIdx.x < off) sh[threadIdx.x] += sh[threadIdx.x + off];
        __syncthreads();
    }
    if (threadIdx.x == 0) g_part[b] = sh[0];
}
__global__ void finalize2_kernel(float* __restrict__ out) {
    __shared__ double sh[128];
    sh[threadIdx.x] = g_part[threadIdx.x];
    __syncthreads();
    for (int off = 64; off >= 1; off >>= 1) {
        if (threadIdx.x < off) sh[threadIdx.x] += sh[threadIdx.x + off];
        __syncthreads();
    }
    if (threadIdx.x == 0)
        out[0] = (float)(0.5 * sh[0] / ((double)N_TOK * (double)DIM));
}

// ---------------------------------------------------------------------------
extern "C" void kernel_launch(void* const* d_in, const int* in_sizes, int n_in,
                              void* d_out, int out_size) {
    const float* X = (const float*)d_in[0];   // embedding_tokens [N, D]
    const float* E = (const float*)d_in[1];   // embeddings       [K, D]
    float* out = (float*)d_out;
    float* out_q   = out + 1;
    float* out_idx = out + 1 + (size_t)N_TOK * DIM;

    static int smem_set = 0;
    if (!smem_set) {
        cudaFuncSetAttribute(coarse_kernel, cudaFuncAttributeMaxDynamicSharedMemorySize, SMEM_TOTAL);
        smem_set = 1;
    }

    prep_kernel<<<N_TOK / 256, 256>>>(X, E);
    reduce_kernel<<<1, 256>>>();
    coarse_kernel<<<(N_TOK / TOK_TILE) * N_QUART, 256, SMEM_TOTAL>>>();
    rescore_output_kernel<<<(N_TOK * 32) / 256, 256>>>(X, E, out_q, out_idx);
    finalize1_kernel<<<128, 256>>>();
    finalize2_kernel<<<1, 128>>>(out);
}

// round 12
// speedup vs baseline: 2.0994x; 1.0373x over previous
#include <cuda_runtime.h>
#include <math_constants.h>
#include <cstdint>

// Problem constants: B=16,T=2048,D=256,K=4096
#define N_TOK 32768
#define DIM   256
#define KCB   4096
#define NKCH  (DIM / 4)     // 64 packed int32 k-chunks per row

#define TOK_TILE  128
#define CODE_TILE 64
#define N_QUART   4                        // code-range quarters per token tile
#define QRANGE    (KCB / N_QUART)          // 1024 codes per CTA
#define N_CTILE   (QRANGE / CODE_TILE)     // 16 tiles per CTA
#define MAX_CAND  192

// ---------------- device scratch (no allocations allowed) -------------------
__device__ float  g_S[N_TOK];
__device__ float  g_c[KCB];
__device__ float  g_loss[N_TOK];
__device__ double g_part[128];
__device__ float  g_sx[N_TOK], g_Lx[N_TOK];
__device__ float  g_se[KCB],  g_Le[KCB];
__device__ float  g_maxse, g_maxLe;
__device__ __align__(16) int g_XqT[NKCH * N_TOK];   // [kchunk][token]  8MB
__device__ __align__(16) int g_EqT[NKCH * KCB];     // [kchunk][code]   1MB
__device__ unsigned short g_cand[N_TOK][MAX_CAND];  // 12MB
__device__ float  g_cand_s[N_TOK][MAX_CAND];        // 24MB coarse scores
__device__ int    g_ncand[N_TOK];

// ---------------- helpers ----------------------------------------------------
__device__ __forceinline__ uint32_t smem_to_u32(const void* p) {
    uint32_t a;
    asm("{ .reg .u64 t; cvta.to.shared.u64 t, %1; cvt.u32.u64 %0, t; }" : "=r"(a) : "l"(p));
    return a;
}
__device__ __forceinline__ void dp4a(int& acc, int a, int b) {
    asm("dp4a.s32.s32 %0, %1, %2, %0;" : "+r"(acc) : "r"(a), "r"(b));
}
__device__ __forceinline__ void cp_async16(uint32_t dst_smem, const void* src) {
    asm volatile("cp.async.cg.shared.global [%0], [%1], 16;" :: "r"(dst_smem), "l"(src) : "memory");
}
__device__ __forceinline__ void cp_commit() { asm volatile("cp.async.commit_group;" ::: "memory"); }
__device__ __forceinline__ void cp_wait0()  { asm volatile("cp.async.wait_group 0;"  ::: "memory"); }
__device__ __forceinline__ int q8(float v, float inv) {
    int q = __float2int_rn(v * inv);
    return max(-127, min(127, q));
}
// rigorous per-token margin: 2*(int8 quant bound on 2m) + fp32 d2-chain slop
__device__ __forceinline__ float token_margin(float sx, float lx, float mse, float mle) {
    return 2.0f * (0.5f * sx * mle + 0.5f * mse * lx + 128.0f * sx * mse) + 3.0e-4f;
}

// ---------------------------------------------------------------------------
// Kernel 1: per-row exact-fp32 sums of squares (bit-matching R2 chain),
// per-row max/L1, int8 quantization into TRANSPOSED packed layout.
// ---------------------------------------------------------------------------
__global__ void prep_kernel(const float* __restrict__ X, const float* __restrict__ E) {
    int i = blockIdx.x * blockDim.x + threadIdx.x;
    if (i < N_TOK) {
        g_ncand[i] = 0;
        const float4* row = reinterpret_cast<const float4*>(X + (size_t)i * DIM);
        float s = 0.0f, mx = 0.0f, l1 = 0.0f;
        #pragma unroll 8
        for (int j = 0; j < DIM / 4; j++) {
            float4 v = row[j];
            s = __fadd_rn(s, __fmul_rn(v.x, v.x));
            s = __fadd_rn(s, __fmul_rn(v.y, v.y));
            s = __fadd_rn(s, __fmul_rn(v.z, v.z));
            s = __fadd_rn(s, __fmul_rn(v.w, v.w));
            float ax = fabsf(v.x), ay = fabsf(v.y), az = fabsf(v.z), aw = fabsf(v.w);
            mx = fmaxf(fmaxf(mx, ax), fmaxf(ay, fmaxf(az, aw)));
            l1 += ax + ay + az + aw;
        }
        g_S[i] = s;
        mx = fmaxf(mx, 1e-30f);
        float inv = 127.0f / mx;
        g_sx[i] = mx / 127.0f;
        g_Lx[i] = l1;
        #pragma unroll 8
        for (int k = 0; k < NKCH; k++) {
            float4 v = row[k];
            int q0 = q8(v.x, inv), q1 = q8(v.y, inv), q2 = q8(v.z, inv), q3 = q8(v.w, inv);
            g_XqT[k * N_TOK + i] = (q0 & 255) | ((q1 & 255) << 8) | ((q2 & 255) << 16) | ((q3 & 255) << 24);
        }
    }
    if (i < KCB) {
        const float4* row = reinterpret_cast<const float4*>(E + (size_t)i * DIM);
        float s = 0.0f, mx = 0.0f, l1 = 0.0f;
        #pragma unroll 8
        for (int j = 0; j < DIM / 4; j++) {
            float4 v = row[j];
            s = __fadd_rn(s, __fmul_rn(v.x, v.x));
            s = __fadd_rn(s, __fmul_rn(v.y, v.y));
            s = __fadd_rn(s, __fmul_rn(v.z, v.z));
            s = __fadd_rn(s, __fmul_rn(v.w, v.w));
            float ax = fabsf(v.x), ay = fabsf(v.y), az = fabsf(v.z), aw = fabsf(v.w);
            mx = fmaxf(fmaxf(mx, ax), fmaxf(ay, fmaxf(az, aw)));
            l1 += ax + ay + az + aw;
        }
        g_c[i] = s;
        mx = fmaxf(mx, 1e-30f);
        float inv = 127.0f / mx;
        g_se[i] = mx / 127.0f;
        g_Le[i] = l1;
        #pragma unroll 8
        for (int k = 0; k < NKCH; k++) {
            float4 v = row[k];
            int q0 = q8(v.x, inv), q1 = q8(v.y, inv), q2 = q8(v.z, inv), q3 = q8(v.w, inv);
            g_EqT[k * KCB + i] = (q0 & 255) | ((q1 & 255) << 8) | ((q2 & 255) << 16) | ((q3 & 255) << 24);
        }
    }
}

// ---------------------------------------------------------------------------
// Kernel 2: global max of se / Le over codes (for rigorous per-token margins).
// ---------------------------------------------------------------------------
__global__ void reduce_kernel() {
    __shared__ float s1[256], s2[256];
    float m1 = 0.0f, m2 = 0.0f;
    for (int j = threadIdx.x; j < KCB; j += 256) {
        m1 = fmaxf(m1, g_se[j]);
        m2 = fmaxf(m2, g_Le[j]);
    }
    s1[threadIdx.x] = m1; s2[threadIdx.x] = m2;
    __syncthreads();
    for (int off = 128; off >= 1; off >>= 1) {
        if (threadIdx.x < off) {
            s1[threadIdx.x] = fmaxf(s1[threadIdx.x], s1[threadIdx.x + off]);
            s2[threadIdx.x] = fmaxf(s2[threadIdx.x], s2[threadIdx.x + off]);
        }
        __syncthreads();
    }
    if (threadIdx.x == 0) { g_maxse = s1[0]; g_maxLe = s2[0]; }
}

// ---------------------------------------------------------------------------
// Kernel 3: int8 dp4a coarse GEMM + margin candidate collection.
// Occupancy-optimized: 8 tokens x 4 codes per thread (32 acc regs),
// CODE_TILE=64 -> smem 66KB, __launch_bounds__(256,3) => 3 CTAs/SM,
// 24 warps/SM (6/SMSP) to keep the dp4a pipe fed.
// Grid = 256 token-tiles x 4 quarters = 1024 CTAs.
// ---------------------------------------------------------------------------
#define SM_X    0                     // int Xs[64][128]            32KB
#define SM_E    32768                 // int Es[2][64][64]          32KB
#define SM_MARG 65536                 // float marg[128]
#define SM_SX   66048                 // float sx[128]
#define SMEM_TOTAL 66560

__global__ __launch_bounds__(256, 3) void coarse_kernel() {
    extern __shared__ __align__(16) char smem[];
    const int tid = threadIdx.x;
    const int tx = tid & 15, ty = tid >> 4;
    const int mb = (blockIdx.x >> 2) * TOK_TILE;       // token base
    const int cq = (blockIdx.x & 3) * QRANGE;          // code-quarter base
    uint32_t sb = smem_to_u32(smem);
    int* Xs = reinterpret_cast<int*>(smem + SM_X);
    int* Es = reinterpret_cast<int*>(smem + SM_E);
    float* marg_s = reinterpret_cast<float*>(smem + SM_MARG);
    float* sx_s = reinterpret_cast<float*>(smem + SM_SX);

    if (tid < TOK_TILE) {
        float sx = g_sx[mb + tid];
        float lx = g_Lx[mb + tid];
        sx_s[tid] = sx;
        marg_s[tid] = token_margin(sx, lx, g_maxse, g_maxLe);
    }

    // X tile: 64 kchunks x 128 tokens (cp.async, contiguous 512B rows)
    #pragma unroll
    for (int k = 0; k < 8; k++) {
        int v = tid + k * 256;
        int row = v >> 5, ch = v & 31;
        cp_async16(sb + SM_X + (row * 128 + ch * 4) * 4,
                   g_XqT + (size_t)row * N_TOK + mb + ch * 4);
    }
    // E tile 0 of this quarter: 64 kchunks x 64 codes (1024 cp16)
    #pragma unroll
    for (int k = 0; k < 4; k++) {
        int v = tid + k * 256;
        int row = v >> 4, ch = v & 15;
        cp_async16(sb + SM_E + (row * 64 + ch * 4) * 4,
                   g_EqT + (size_t)row * KCB + cq + ch * 4);
    }
    cp_commit();
    cp_wait0();
    __syncthreads();

    float sxv[8], margv[8], runmin[8];
    #pragma unroll
    for (int i = 0; i < 8; i++) {
        sxv[i]   = sx_s[ty * 8 + i];
        margv[i] = marg_s[ty * 8 + i];
        runmin[i] = CUDART_INF_F;
    }

    for (int ct = 0; ct < N_CTILE; ct++) {
        const int cur = ct & 1;

        if (ct < N_CTILE - 1) {
            #pragma unroll
            for (int k = 0; k < 4; k++) {
                int v = tid + k * 256;
                int row = v >> 4, ch = v & 15;
                cp_async16(sb + SM_E + ((cur ^ 1) * 4096 + row * 64 + ch * 4) * 4,
                           g_EqT + (size_t)row * KCB + cq + (ct + 1) * CODE_TILE + ch * 4);
            }
            cp_commit();
        }

        int acc[8][4];
        #pragma unroll
        for (int i = 0; i < 8; i++)
            #pragma unroll
            for (int j = 0; j < 4; j++) acc[i][j] = 0;

        const int* eb = Es + cur * 4096;
        #pragma unroll 4
        for (int kc = 0; kc < NKCH; kc++) {
            int4 a0 = *reinterpret_cast<const int4*>(Xs + kc * 128 + ty * 8);
            int4 a1 = *reinterpret_cast<const int4*>(Xs + kc * 128 + ty * 8 + 4);
            int4 b0 = *reinterpret_cast<const int4*>(eb + kc * 64 + tx * 4);
            int aw[8] = {a0.x, a0.y, a0.z, a0.w, a1.x, a1.y, a1.z, a1.w};
            int bw[4] = {b0.x, b0.y, b0.z, b0.w};
            #pragma unroll
            for (int i = 0; i < 8; i++)
                #pragma unroll
                for (int j = 0; j < 4; j++)
                    dp4a(acc[i][j], aw[i], bw[j]);
        }

        // epilogue: s_hat, half-warp tile-min reduce, running-min collection
        float se4[4], c4[4];
        #pragma unroll
        for (int j = 0; j < 4; j++) {
            int code = cq + ct * CODE_TILE + tx * 4 + j;
            se4[j] = __ldg(&g_se[code]);
            c4[j]  = __ldg(&g_c[code]);
        }
        #pragma unroll
        for (int i = 0; i < 8; i++) {
            const float nsx = -2.0f * sxv[i];
            float s[4];
            float tmin = CUDART_INF_F;
            #pragma unroll
            for (int j = 0; j < 4; j++) {
                s[j] = fmaf(nsx * se4[j], (float)acc[i][j], c4[j]);
                tmin = fminf(tmin, s[j]);
            }
            // reduce tile-min across the 16 code-lanes (same half-warp)
            #pragma unroll
            for (int off = 8; off >= 1; off >>= 1)
                tmin = fminf(tmin, __shfl_xor_sync(0xffffffffu, tmin, off));
            runmin[i] = fminf(runmin[i], tmin);
            const float th = runmin[i] + margv[i];
            bool any = false;
            #pragma unroll
            for (int j = 0; j < 4; j++) any |= (s[j] <= th);
            if (any) {
                const int token = mb + ty * 8 + i;
                #pragma unroll
                for (int j = 0; j < 4; j++) {
                    if (s[j] <= th) {
                        int code = cq + ct * CODE_TILE + tx * 4 + j;
                        int p = atomicAdd(&g_ncand[token], 1);
                        if (p < MAX_CAND) {
                            g_cand[token][p] = (unsigned short)code;
                            g_cand_s[token][p] = s[j];
                        }
                    }
                }
            }
        }

        if (ct < N_CTILE - 1) cp_wait0();
        __syncthreads();
    }
}

// ---------------------------------------------------------------------------
// Kernel 4: survivor-filtered exact rescore + gather + STE output + loss.
// One warp per token; up to 6 candidate slots per lane (MAX_CAND=192).
//  - survivors = candidates with coarse s <= global finalmin + marg (provably
//    contains the exact argmin and all exact ties).
//  - 1 survivor  -> it IS the argmin; no dot products.
//  - >1 survivor -> exact R2-chain d2 on surviving slots, lexicographic min.
//  - overflow (n > MAX_CAND, ~never) -> exact full scan (also exact).
// ---------------------------------------------------------------------------
#define NSLOT (MAX_CAND / 32)   // 6

__global__ void rescore_output_kernel(const float* __restrict__ X, const float* __restrict__ E,
                                      float* __restrict__ out_q, float* __restrict__ out_idx_f) {
    int token = (blockIdx.x * blockDim.x + threadIdx.x) >> 5;
    int lane = threadIdx.x & 31;
    if (token >= N_TOK) return;
    int n = g_ncand[token];
    float S = g_S[token];
    const float4* xr = reinterpret_cast<const float4*>(X + (size_t)token * DIM);

    int besti = 0x7fffffff;

    if (n <= MAX_CAND) {
        float sc[NSLOT];
        int   cd[NSLOT];
        #pragma unroll
        for (int q = 0; q < NSLOT; q++) {
            int idx = lane + q * 32;
            if (idx < n) { cd[q] = g_cand[token][idx]; sc[q] = g_cand_s[token][idx]; }
            else         { cd[q] = 0x7fffffff;         sc[q] = CUDART_INF_F; }
        }
        float fm = CUDART_INF_F;
        #pragma unroll
        for (int q = 0; q < NSLOT; q++) fm = fminf(fm, sc[q]);
        #pragma unroll
        for (int off = 16; off >= 1; off >>= 1)
            fm = fminf(fm, __shfl_xor_sync(0xffffffffu, fm, off));
        const float marg = token_margin(g_sx[token], g_Lx[token], g_maxse, g_maxLe);
        const float th = fm + marg;

        bool sv[NSLOT];
        int tot = 0;
        #pragma unroll
        for (int q = 0; q < NSLOT; q++) {
            sv[q] = (sc[q] <= th);
            tot += __popc(__ballot_sync(0xffffffffu, sv[q]));
        }

        if (tot == 1) {
            int myc = 0x7fffffff;
            #pragma unroll
            for (int q = 0; q < NSLOT; q++) if (sv[q]) myc = cd[q];
            #pragma unroll
            for (int off = 16; off >= 1; off >>= 1)
                myc = min(myc, __shfl_xor_sync(0xffffffffu, myc, off));
            besti = myc;
        } else {
            float bestv = CUDART_INF_F;
            #pragma unroll
            for (int q = 0; q < NSLOT; q++) {
                if (sv[q]) {
                    const float4* er = reinterpret_cast<const float4*>(E + (size_t)cd[q] * DIM);
                    float m = 0.0f;
                    #pragma unroll 8
                    for (int k = 0; k < DIM / 4; k++) {
                        float4 x = xr[k], e = er[k];
                        m = fmaf(x.x, e.x, m); m = fmaf(x.y, e.y, m);
                        m = fmaf(x.z, e.z, m); m = fmaf(x.w, e.w, m);
                    }
                    float t = fmaf(-2.0f, m, S);
                    float d2 = __fadd_rn(t, g_c[cd[q]]);
                    if (d2 < bestv || (d2 == bestv && cd[q] < besti)) { bestv = d2; besti = cd[q]; }
                }
            }
            #pragma unroll
            for (int off = 16; off >= 1; off >>= 1) {
                float ov = __shfl_xor_sync(0xffffffffu, bestv, off);
                int   oi = __shfl_xor_sync(0xffffffffu, besti, off);
                if (ov < bestv || (ov == bestv && oi < besti)) { bestv = ov; besti = oi; }
            }
            besti = __shfl_sync(0xffffffffu, besti, 0);
        }
    } else {
        // overflow fallback: exact scan of all codes (probability ~0)
        float bestv = CUDART_INF_F;
        for (int code = lane; code < KCB; code += 32) {
            const float4* er = reinterpret_cast<const float4*>(E + (size_t)code * DIM);
            float m = 0.0f;
            #pragma unroll 8
            for (int k = 0; k < DIM / 4; k++) {
                float4 x = xr[k], e = er[k];
                m = fmaf(x.x, e.x, m); m = fmaf(x.y, e.y, m);
                m = fmaf(x.z, e.z, m); m = fmaf(x.w, e.w, m);
            }
            float t = fmaf(-2.0f, m, S);
            float d2 = __fadd_rn(t, g_c[code]);
            if (d2 < bestv || (d2 == bestv && code < besti)) { bestv = d2; besti = code; }
        }
        #pragma unroll
        for (int off = 16; off >= 1; off >>= 1) {
            float ov = __shfl_xor_sync(0xffffffffu, bestv, off);
            int   oi = __shfl_xor_sync(0xffffffffu, besti, off);
            if (ov < bestv || (ov == bestv && oi < besti)) { bestv = ov; besti = oi; }
        }
        besti = __shfl_sync(0xffffffffu, besti, 0);
    }

    // gather + straight-through + loss (bit-exact R2 arithmetic)
    const float4* er = reinterpret_cast<const float4*>(E + (size_t)besti * DIM);
    float* qr = out_q + (size_t)token * DIM;   // 4B-aligned only -> scalar stores
    float ls = 0.0f;
    #pragma unroll
    for (int j = lane; j < DIM / 4; j += 32) {
        float4 x = xr[j], e = er[j];
        float4 d, o;
        d.x = __fadd_rn(e.x, -x.x); d.y = __fadd_rn(e.y, -x.y);
        d.z = __fadd_rn(e.z, -x.z); d.w = __fadd_rn(e.w, -x.w);
        ls = __fadd_rn(ls, __fmul_rn(d.x, d.x));
        ls = __fadd_rn(ls, __fmul_rn(d.y, d.y));
        ls = __fadd_rn(ls, __fmul_rn(d.z, d.z));
        ls = __fadd_rn(ls, __fmul_rn(d.w, d.w));
        o.x = __fadd_rn(x.x, d.x); o.y = __fadd_rn(x.y, d.y);
        o.z = __fadd_rn(x.z, d.z); o.w = __fadd_rn(x.w, d.w);
        qr[j * 4 + 0] = o.x;
        qr[j * 4 + 1] = o.y;
        qr[j * 4 + 2] = o.z;
        qr[j * 4 + 3] = o.w;
    }
    #pragma unroll
    for (int off = 16; off >= 1; off >>= 1)
        ls = __fadd_rn(ls, __shfl_xor_sync(0xffffffffu, ls, off));
    if (lane == 0) {
        g_loss[token] = ls;
        out_idx_f[token] = (float)besti;
    }
}

// ---------------------------------------------------------------------------
// Kernels 5+6: two-stage deterministic double-precision loss reduction.
// ---------------------------------------------------------------------------
__global__ void finalize1_kernel() {
    __shared__ double sh[256];
    int b = blockIdx.x;
    sh[threadIdx.x] = (double)g_loss[b * 256 + threadIdx.x];
    __syncthreads();
    for (int off = 128; off >= 1; off >>= 1) {
        if (threadIdx.x < off) sh[threadIdx.x] += sh[threadIdx.x + off];
        __syncthreads();
    }
    if (threadIdx.x == 0) g_part[b] = sh[0];
}
__global__ void finalize2_kernel(float* __restrict__ out) {
    __shared__ double sh[128];
    sh[threadIdx.x] = g_part[threadIdx.x];
    __syncthreads();
    for (int off = 64; off >= 1; off >>= 1) {
        if (threadIdx.x < off) sh[threadIdx.x] += sh[threadIdx.x + off];
        __syncthreads();
    }
    if (threadIdx.x == 0)
        out[0] = (float)(0.5 * sh[0] / ((double)N_TOK * (double)DIM));
}

// ---------------------------------------------------------------------------
extern "C" void kernel_launch(void* const* d_in, const int* in_sizes, int n_in,
                              void* d_out, int out_size) {
    const float* X = (const float*)d_in[0];   // embedding_tokens [N, D]
    const float* E = (const float*)d_in[1];   // embeddings       [K, D]
    float* out = (float*)d_out;
    float* out_q   = out + 1;
    float* out_idx = out + 1 + (size_t)N_TOK * DIM;

    static int smem_set = 0;
    if (!smem_set) {
        cudaFuncSetAttribute(coarse_kernel, cudaFuncAttributeMaxDynamicSharedMemorySize, SMEM_TOTAL);
        smem_set = 1;
    }

    prep_kernel<<<N_TOK / 256, 256>>>(X, E);
    reduce_kernel<<<1, 256>>>();
    coarse_kernel<<<(N_TOK / TOK_TILE) * N_QUART, 256, SMEM_TOTAL>>>();
    rescore_output_kernel<<<(N_TOK * 32) / 256, 256>>>(X, E, out_q, out_idx);
    finalize1_kernel<<<128, 256>>>();
    finalize2_kernel<<<1, 128>>>(out);
}

// round 13
// speedup vs baseline: 2.1333x; 1.0162x over previous
#include <cuda_runtime.h>
#include <math_constants.h>
#include <cstdint>

// Problem constants: B=16,T=2048,D=256,K=4096
#define N_TOK 32768
#define DIM   256
#define KCB   4096
#define NKCH  (DIM / 4)     // 64 packed int32 k-chunks per row

#define TOK_TILE  128
#define CODE_TILE 128
#define N_QUART   4                        // code-range quarters per token tile
#define QRANGE    (KCB / N_QUART)          // 1024 codes per CTA
#define N_CTILE   (QRANGE / CODE_TILE)     // 8 tiles per CTA
#define MAX_CAND  192

// ---------------- device scratch (no allocations allowed) -------------------
__device__ float  g_S[N_TOK];
__device__ float  g_c[KCB];
__device__ float2 g_sec[KCB];              // {-2*se, c} for coarse epilogue
__device__ float  g_loss[N_TOK];
__device__ double g_part[128];
__device__ float  g_sx[N_TOK], g_Lx[N_TOK];
__device__ float  g_se[KCB],  g_Le[KCB];
__device__ float  g_maxse, g_maxLe;
__device__ __align__(16) int g_XqT[NKCH * N_TOK];   // [kchunk][token]  8MB
__device__ __align__(16) int g_EqT[NKCH * KCB];     // [kchunk][code]   1MB
__device__ unsigned short g_cand[N_TOK][MAX_CAND];  // 12MB
__device__ float  g_cand_s[N_TOK][MAX_CAND];        // 24MB coarse scores
__device__ int    g_ncand[N_TOK];

// ---------------- helpers ----------------------------------------------------
__device__ __forceinline__ uint32_t smem_to_u32(const void* p) {
    uint32_t a;
    asm("{ .reg .u64 t; cvta.to.shared.u64 t, %1; cvt.u32.u64 %0, t; }" : "=r"(a) : "l"(p));
    return a;
}
__device__ __forceinline__ void dp4a(int& acc, int a, int b) {
    asm("dp4a.s32.s32 %0, %1, %2, %0;" : "+r"(acc) : "r"(a), "r"(b));
}
__device__ __forceinline__ void cp_async16(uint32_t dst_smem, const void* src) {
    asm volatile("cp.async.cg.shared.global [%0], [%1], 16;" :: "r"(dst_smem), "l"(src) : "memory");
}
__device__ __forceinline__ void cp_commit() { asm volatile("cp.async.commit_group;" ::: "memory"); }
__device__ __forceinline__ void cp_wait0()  { asm volatile("cp.async.wait_group 0;"  ::: "memory"); }
__device__ __forceinline__ int q8(float v, float inv) {
    int q = __float2int_rn(v * inv);
    return max(-127, min(127, q));
}
// rigorous per-token margin: 2*(int8 quant bound on 2m) + fp32 d2-chain slop
__device__ __forceinline__ float token_margin(float sx, float lx, float mse, float mle) {
    return 2.0f * (0.5f * sx * mle + 0.5f * mse * lx + 128.0f * sx * mse) + 3.0e-4f;
}

// ---------------------------------------------------------------------------
// Kernel 1: per-row exact-fp32 sums of squares (bit-matching R2 chain),
// per-row max/L1, int8 quantization into TRANSPOSED packed layout.
// Also builds the g_sec = {-2*se, c} table for the coarse epilogue.
// ---------------------------------------------------------------------------
__global__ void prep_kernel(const float* __restrict__ X, const float* __restrict__ E) {
    int i = blockIdx.x * blockDim.x + threadIdx.x;
    if (i < N_TOK) {
        g_ncand[i] = 0;
        const float4* row = reinterpret_cast<const float4*>(X + (size_t)i * DIM);
        float s = 0.0f, mx = 0.0f, l1 = 0.0f;
        #pragma unroll 8
        for (int j = 0; j < DIM / 4; j++) {
            float4 v = row[j];
            s = __fadd_rn(s, __fmul_rn(v.x, v.x));
            s = __fadd_rn(s, __fmul_rn(v.y, v.y));
            s = __fadd_rn(s, __fmul_rn(v.z, v.z));
            s = __fadd_rn(s, __fmul_rn(v.w, v.w));
            float ax = fabsf(v.x), ay = fabsf(v.y), az = fabsf(v.z), aw = fabsf(v.w);
            mx = fmaxf(fmaxf(mx, ax), fmaxf(ay, fmaxf(az, aw)));
            l1 += ax + ay + az + aw;
        }
        g_S[i] = s;
        mx = fmaxf(mx, 1e-30f);
        float inv = 127.0f / mx;
        g_sx[i] = mx / 127.0f;
        g_Lx[i] = l1;
        #pragma unroll 8
        for (int k = 0; k < NKCH; k++) {
            float4 v = row[k];
            int q0 = q8(v.x, inv), q1 = q8(v.y, inv), q2 = q8(v.z, inv), q3 = q8(v.w, inv);
            g_XqT[k * N_TOK + i] = (q0 & 255) | ((q1 & 255) << 8) | ((q2 & 255) << 16) | ((q3 & 255) << 24);
        }
    }
    if (i < KCB) {
        const float4* row = reinterpret_cast<const float4*>(E + (size_t)i * DIM);
        float s = 0.0f, mx = 0.0f, l1 = 0.0f;
        #pragma unroll 8
        for (int j = 0; j < DIM / 4; j++) {
            float4 v = row[j];
            s = __fadd_rn(s, __fmul_rn(v.x, v.x));
            s = __fadd_rn(s, __fmul_rn(v.y, v.y));
            s = __fadd_rn(s, __fmul_rn(v.z, v.z));
            s = __fadd_rn(s, __fmul_rn(v.w, v.w));
            float ax = fabsf(v.x), ay = fabsf(v.y), az = fabsf(v.z), aw = fabsf(v.w);
            mx = fmaxf(fmaxf(mx, ax), fmaxf(ay, fmaxf(az, aw)));
            l1 += ax + ay + az + aw;
        }
        g_c[i] = s;
        mx = fmaxf(mx, 1e-30f);
        float inv = 127.0f / mx;
        float se = mx / 127.0f;
        g_se[i] = se;
        g_Le[i] = l1;
        g_sec[i] = make_float2(-2.0f * se, s);
        #pragma unroll 8
        for (int k = 0; k < NKCH; k++) {
            float4 v = row[k];
            int q0 = q8(v.x, inv), q1 = q8(v.y, inv), q2 = q8(v.z, inv), q3 = q8(v.w, inv);
            g_EqT[k * KCB + i] = (q0 & 255) | ((q1 & 255) << 8) | ((q2 & 255) << 16) | ((q3 & 255) << 24);
        }
    }
}

// ---------------------------------------------------------------------------
// Kernel 2: global max of se / Le over codes (for rigorous per-token margins).
// ---------------------------------------------------------------------------
__global__ void reduce_kernel() {
    __shared__ float s1[256], s2[256];
    float m1 = 0.0f, m2 = 0.0f;
    for (int j = threadIdx.x; j < KCB; j += 256) {
        m1 = fmaxf(m1, g_se[j]);
        m2 = fmaxf(m2, g_Le[j]);
    }
    s1[threadIdx.x] = m1; s2[threadIdx.x] = m2;
    __syncthreads();
    for (int off = 128; off >= 1; off >>= 1) {
        if (threadIdx.x < off) {
            s1[threadIdx.x] = fmaxf(s1[threadIdx.x], s1[threadIdx.x + off]);
            s2[threadIdx.x] = fmaxf(s2[threadIdx.x], s2[threadIdx.x + off]);
        }
        __syncthreads();
    }
    if (threadIdx.x == 0) { g_maxse = s1[0]; g_maxLe = s2[0]; }
}

// ---------------------------------------------------------------------------
// Kernel 3: int8 dp4a coarse GEMM + margin candidate collection.
// 512 threads = 16 token-groups(ty) x 32 code-lanes(tx); 8 tokens x 4 codes
// per thread; CODE_TILE=128 (8 tiles/CTA). smem ~97.5KB => 2 CTAs/SM
// = 32 warps/SM (8/SMSP). Each warp owns one 8-token group's 32 code-lanes:
// tile-min = full-warp shfl reduce. Grid = 256 token-tiles x 4 quarters.
// ---------------------------------------------------------------------------
#define SM_X    0                     // int Xs[64][128]            32KB
#define SM_E    32768                 // int Es[2][64][128]         64KB
#define SM_MARG 98304                 // float marg[128]
#define SM_SX   98816                 // float sx[128]
#define SMEM_TOTAL 99328

__global__ __launch_bounds__(512, 2) void coarse_kernel() {
    extern __shared__ __align__(16) char smem[];
    const int tid = threadIdx.x;
    const int tx = tid & 31, ty = tid >> 5;            // 32 code lanes x 16 groups
    const int mb = (blockIdx.x >> 2) * TOK_TILE;       // token base
    const int cq = (blockIdx.x & 3) * QRANGE;          // code-quarter base
    uint32_t sb = smem_to_u32(smem);
    int* Xs = reinterpret_cast<int*>(smem + SM_X);
    int* Es = reinterpret_cast<int*>(smem + SM_E);
    float* marg_s = reinterpret_cast<float*>(smem + SM_MARG);
    float* sx_s = reinterpret_cast<float*>(smem + SM_SX);

    if (tid < TOK_TILE) {
        float sx = g_sx[mb + tid];
        float lx = g_Lx[mb + tid];
        sx_s[tid] = sx;
        marg_s[tid] = token_margin(sx, lx, g_maxse, g_maxLe);
    }

    // X tile: 64 kchunks x 128 tokens = 2048 cp16 (4 per thread)
    #pragma unroll
    for (int k = 0; k < 4; k++) {
        int v = tid + k * 512;
        int row = v >> 5, ch = v & 31;
        cp_async16(sb + SM_X + (row * 128 + ch * 4) * 4,
                   g_XqT + (size_t)row * N_TOK + mb + ch * 4);
    }
    // E tile 0: 64 kchunks x 128 codes = 2048 cp16
    #pragma unroll
    for (int k = 0; k < 4; k++) {
        int v = tid + k * 512;
        int row = v >> 5, ch = v & 31;
        cp_async16(sb + SM_E + (row * 128 + ch * 4) * 4,
                   g_EqT + (size_t)row * KCB + cq + ch * 4);
    }
    cp_commit();
    cp_wait0();
    __syncthreads();

    float sxv[8], margv[8], runmin[8];
    #pragma unroll
    for (int i = 0; i < 8; i++) {
        sxv[i]   = sx_s[ty * 8 + i];
        margv[i] = marg_s[ty * 8 + i];
        runmin[i] = CUDART_INF_F;
    }

    for (int ct = 0; ct < N_CTILE; ct++) {
        const int cur = ct & 1;

        if (ct < N_CTILE - 1) {
            #pragma unroll
            for (int k = 0; k < 4; k++) {
                int v = tid + k * 512;
                int row = v >> 5, ch = v & 31;
                cp_async16(sb + SM_E + ((cur ^ 1) * 8192 + row * 128 + ch * 4) * 4,
                           g_EqT + (size_t)row * KCB + cq + (ct + 1) * CODE_TILE + ch * 4);
            }
            cp_commit();
        }

        int acc[8][4];
        #pragma unroll
        for (int i = 0; i < 8; i++)
            #pragma unroll
            for (int j = 0; j < 4; j++) acc[i][j] = 0;

        const int* eb = Es + cur * 8192;
        #pragma unroll 4
        for (int kc = 0; kc < NKCH; kc++) {
            int4 a0 = *reinterpret_cast<const int4*>(Xs + kc * 128 + ty * 8);
            int4 a1 = *reinterpret_cast<const int4*>(Xs + kc * 128 + ty * 8 + 4);
            int4 b0 = *reinterpret_cast<const int4*>(eb + kc * 128 + tx * 4);
            int aw[8] = {a0.x, a0.y, a0.z, a0.w, a1.x, a1.y, a1.z, a1.w};
            int bw[4] = {b0.x, b0.y, b0.z, b0.w};
            #pragma unroll
            for (int i = 0; i < 8; i++)
                #pragma unroll
                for (int j = 0; j < 4; j++)
                    dp4a(acc[i][j], aw[i], bw[j]);
        }

        // epilogue: s_hat, full-warp tile-min reduce, running-min collection
        float2 sec4[4];
        #pragma unroll
        for (int j = 0; j < 4; j++)
            sec4[j] = __ldg(&g_sec[cq + ct * CODE_TILE + tx * 4 + j]);
        #pragma unroll
        for (int i = 0; i < 8; i++) {
            const float sx = sxv[i];
            float s[4];
            float tmin = CUDART_INF_F;
            #pragma unroll
            for (int j = 0; j < 4; j++) {
                s[j] = fmaf(sx * sec4[j].x, (float)acc[i][j], sec4[j].y);
                tmin = fminf(tmin, s[j]);
            }
            // tile-min across all 32 code-lanes of this warp
            #pragma unroll
            for (int off = 16; off >= 1; off >>= 1)
                tmin = fminf(tmin, __shfl_xor_sync(0xffffffffu, tmin, off));
            runmin[i] = fminf(runmin[i], tmin);
            const float th = runmin[i] + margv[i];
            bool any = false;
            #pragma unroll
            for (int j = 0; j < 4; j++) any |= (s[j] <= th);
            if (any) {
                const int token = mb + ty * 8 + i;
                #pragma unroll
                for (int j = 0; j < 4; j++) {
                    if (s[j] <= th) {
                        int code = cq + ct * CODE_TILE + tx * 4 + j;
                        int p = atomicAdd(&g_ncand[token], 1);
                        if (p < MAX_CAND) {
                            g_cand[token][p] = (unsigned short)code;
                            g_cand_s[token][p] = s[j];
                        }
                    }
                }
            }
        }

        if (ct < N_CTILE - 1) cp_wait0();
        __syncthreads();
    }
}

// ---------------------------------------------------------------------------
// Kernel 4: survivor-filtered exact rescore + gather + STE output + loss.
// One warp per token; up to 6 candidate slots per lane (MAX_CAND=192).
//  - survivors = candidates with coarse s <= global finalmin + marg (provably
//    contains the exact argmin and all exact ties).
//  - 1 survivor  -> it IS the argmin; no dot products.
//  - >1 survivor -> exact R2-chain d2 on surviving slots, lexicographic min.
//  - overflow (n > MAX_CAND, ~never) -> exact full scan (also exact).
// ---------------------------------------------------------------------------
#define NSLOT (MAX_CAND / 32)   // 6

__global__ void rescore_output_kernel(const float* __restrict__ X, const float* __restrict__ E,
                                      float* __restrict__ out_q, float* __restrict__ out_idx_f) {
    int token = (blockIdx.x * blockDim.x + threadIdx.x) >> 5;
    int lane = threadIdx.x & 31;
    if (token >= N_TOK) return;
    int n = g_ncand[token];
    float S = g_S[token];
    const float4* xr = reinterpret_cast<const float4*>(X + (size_t)token * DIM);

    int besti = 0x7fffffff;

    if (n <= MAX_CAND) {
        float sc[NSLOT];
        int   cd[NSLOT];
        #pragma unroll
        for (int q = 0; q < NSLOT; q++) {
            int idx = lane + q * 32;
            if (idx < n) { cd[q] = g_cand[token][idx]; sc[q] = g_cand_s[token][idx]; }
            else         { cd[q] = 0x7fffffff;         sc[q] = CUDART_INF_F; }
        }
        float fm = CUDART_INF_F;
        #pragma unroll
        for (int q = 0; q < NSLOT; q++) fm = fminf(fm, sc[q]);
        #pragma unroll
        for (int off = 16; off >= 1; off >>= 1)
            fm = fminf(fm, __shfl_xor_sync(0xffffffffu, fm, off));
        const float marg = token_margin(g_sx[token], g_Lx[token], g_maxse, g_maxLe);
        const float th = fm + marg;

        bool sv[NSLOT];
        int tot = 0;
        #pragma unroll
        for (int q = 0; q < NSLOT; q++) {
            sv[q] = (sc[q] <= th);
            tot += __popc(__ballot_sync(0xffffffffu, sv[q]));
        }

        if (tot == 1) {
            int myc = 0x7fffffff;
            #pragma unroll
            for (int q = 0; q < NSLOT; q++) if (sv[q]) myc = cd[q];
            #pragma unroll
            for (int off = 16; off >= 1; off >>= 1)
                myc = min(myc, __shfl_xor_sync(0xffffffffu, myc, off));
            besti = myc;
        } else {
            float bestv = CUDART_INF_F;
            #pragma unroll
            for (int q = 0; q < NSLOT; q++) {
                if (sv[q]) {
                    const float4* er = reinterpret_cast<const float4*>(E + (size_t)cd[q] * DIM);
                    float m = 0.0f;
                    #pragma unroll 8
                    for (int k = 0; k < DIM / 4; k++) {
                        float4 x = xr[k], e = er[k];
                        m = fmaf(x.x, e.x, m); m = fmaf(x.y, e.y, m);
                        m = fmaf(x.z, e.z, m); m = fmaf(x.w, e.w, m);
                    }
                    float t = fmaf(-2.0f, m, S);
                    float d2 = __fadd_rn(t, g_c[cd[q]]);
                    if (d2 < bestv || (d2 == bestv && cd[q] < besti)) { bestv = d2; besti = cd[q]; }
                }
            }
            #pragma unroll
            for (int off = 16; off >= 1; off >>= 1) {
                float ov = __shfl_xor_sync(0xffffffffu, bestv, off);
                int   oi = __shfl_xor_sync(0xffffffffu, besti, off);
                if (ov < bestv || (ov == bestv && oi < besti)) { bestv = ov; besti = oi; }
            }
            besti = __shfl_sync(0xffffffffu, besti, 0);
        }
    } else {
        // overflow fallback: exact scan of all codes (probability ~0)
        float bestv = CUDART_INF_F;
        for (int code = lane; code < KCB; code += 32) {
            const float4* er = reinterpret_cast<const float4*>(E + (size_t)code * DIM);
            float m = 0.0f;
            #pragma unroll 8
            for (int k = 0; k < DIM / 4; k++) {
                float4 x = xr[k], e = er[k];
                m = fmaf(x.x, e.x, m); m = fmaf(x.y, e.y, m);
                m = fmaf(x.z, e.z, m); m = fmaf(x.w, e.w, m);
            }
            float t = fmaf(-2.0f, m, S);
            float d2 = __fadd_rn(t, g_c[code]);
            if (d2 < bestv || (d2 == bestv && code < besti)) { bestv = d2; besti = code; }
        }
        #pragma unroll
        for (int off = 16; off >= 1; off >>= 1) {
            float ov = __shfl_xor_sync(0xffffffffu, bestv, off);
            int   oi = __shfl_xor_sync(0xffffffffu, besti, off);
            if (ov < bestv || (ov == bestv && oi < besti)) { bestv = ov; besti = oi; }
        }
        besti = __shfl_sync(0xffffffffu, besti, 0);
    }

    // gather + straight-through + loss (bit-exact R2 arithmetic)
    const float4* er = reinterpret_cast<const float4*>(E + (size_t)besti * DIM);
    float* qr = out_q + (size_t)token * DIM;   // 4B-aligned only -> scalar stores
    float ls = 0.0f;
    #pragma unroll
    for (int j = lane; j < DIM / 4; j += 32) {
        float4 x = xr[j], e = er[j];
        float4 d, o;
        d.x = __fadd_rn(e.x, -x.x); d.y = __fadd_rn(e.y, -x.y);
        d.z = __fadd_rn(e.z, -x.z); d.w = __fadd_rn(e.w, -x.w);
        ls = __fadd_rn(ls, __fmul_rn(d.x, d.x));
        ls = __fadd_rn(ls, __fmul_rn(d.y, d.y));
        ls = __fadd_rn(ls, __fmul_rn(d.z, d.z));
        ls = __fadd_rn(ls, __fmul_rn(d.w, d.w));
        o.x = __fadd_rn(x.x, d.x); o.y = __fadd_rn(x.y, d.y);
        o.z = __fadd_rn(x.z, d.z); o.w = __fadd_rn(x.w, d.w);
        qr[j * 4 + 0] = o.x;
        qr[j * 4 + 1] = o.y;
        qr[j * 4 + 2] = o.z;
        qr[j * 4 + 3] = o.w;
    }
    #pragma unroll
    for (int off = 16; off >= 1; off >>= 1)
        ls = __fadd_rn(ls, __shfl_xor_sync(0xffffffffu, ls, off));
    if (lane == 0) {
        g_loss[token] = ls;
        out_idx_f[token] = (float)besti;
    }
}

// ---------------------------------------------------------------------------
// Kernels 5+6: two-stage deterministic double-precision loss reduction.
// ---------------------------------------------------------------------------
__global__ void finalize1_kernel() {
    __shared__ double sh[256];
    int b = blockIdx.x;
    sh[threadIdx.x] = (double)g_loss[b * 256 + threadIdx.x];
    __syncthreads();
    for (int off = 128; off >= 1; off >>= 1) {
        if (threadIdx.x < off) sh[threadIdx.x] += sh[threadIdx.x + off];
        __syncthreads();
    }
    if (threadIdx.x == 0) g_part[b] = sh[0];
}
__global__ void finalize2_kernel(float* __restrict__ out) {
    __shared__ double sh[128];
    sh[threadIdx.x] = g_part[threadIdx.x];
    __syncthreads();
    for (int off = 64; off >= 1; off >>= 1) {
        if (threadIdx.x < off) sh[threadIdx.x] += sh[threadIdx.x + off];
        __syncthreads();
    }
    if (threadIdx.x == 0)
        out[0] = (float)(0.5 * sh[0] / ((double)N_TOK * (double)DIM));
}

// ---------------------------------------------------------------------------
extern "C" void kernel_launch(void* const* d_in, const int* in_sizes, int n_in,
                              void* d_out, int out_size) {
    const float* X = (const float*)d_in[0];   // embedding_tokens [N, D]
    const float* E = (const float*)d_in[1];   // embeddings       [K, D]
    float* out = (float*)d_out;
    float* out_q   = out + 1;
    float* out_idx = out + 1 + (size_t)N_TOK * DIM;

    static int smem_set = 0;
    if (!smem_set) {
        cudaFuncSetAttribute(coarse_kernel, cudaFuncAttributeMaxDynamicSharedMemorySize, SMEM_TOTAL);
        smem_set = 1;
    }

    prep_kernel<<<N_TOK / 256, 256>>>(X, E);
    reduce_kernel<<<1, 256>>>();
    coarse_kernel<<<(N_TOK / TOK_TILE) * N_QUART, 512, SMEM_TOTAL>>>();
    rescore_output_kernel<<<(N_TOK * 32) / 256, 256>>>(X, E, out_q, out_idx);
    finalize1_kernel<<<128, 256>>>();
    finalize2_kernel<<<1, 128>>>(out);
}